// round 2
// baseline (speedup 1.0000x reference)
#include <cuda_runtime.h>
#include <cstdint>

#define EMBED 1024
#define NHEAD 16
#define HDIM  64
#define BATCH 2
#define SEQ   2048
#define MROWS (BATCH*SEQ)   // 4096

// Scratch (allocation-free rule: __device__ globals)
__device__ float g_q[BATCH*NHEAD*SEQ*HDIM];   // [B,H,T,D]
__device__ float g_k[BATCH*NHEAD*SEQ*HDIM];
__device__ float g_v[BATCH*NHEAD*SEQ*HDIM];
__device__ float g_ao[MROWS*EMBED];           // attention out, [B,T,E]

// ---------------------------------------------------------------------------
// SGEMM: C = A @ W^T + bias.   A:[M=4096,K=1024] row-major, W:[N=1024,K] row-major.
// 128x128 tile, BK=8, 256 threads, 8x8 per thread.
// BHTD=true: scatter output to [B,H,T,D] (m=b*T+t, n=h*D+d).
// ---------------------------------------------------------------------------
template<bool BHTD>
__global__ __launch_bounds__(256) void sgemm_bias(
    const float* __restrict__ A, const float* __restrict__ W,
    const float* __restrict__ bias, float* __restrict__ C)
{
    const int K = EMBED;
    __shared__ float As[8][132];
    __shared__ float Bs[8][132];

    int tid = threadIdx.x;
    int tx = tid & 15, ty = tid >> 4;
    int m0 = blockIdx.y * 128;
    int n0 = blockIdx.x * 128;

    int lrow = tid >> 1;           // 0..127
    int lkq  = (tid & 1) * 4;      // 0 or 4

    const float* Ap = A + (size_t)(m0 + lrow) * K + lkq;
    const float* Wp = W + (size_t)(n0 + lrow) * K + lkq;

    float acc[8][8];
    #pragma unroll
    for (int i = 0; i < 8; i++)
        #pragma unroll
        for (int j = 0; j < 8; j++) acc[i][j] = 0.f;

    for (int k0 = 0; k0 < K; k0 += 8) {
        float4 a4 = *reinterpret_cast<const float4*>(Ap + k0);
        float4 b4 = *reinterpret_cast<const float4*>(Wp + k0);
        __syncthreads();
        As[lkq+0][lrow] = a4.x; As[lkq+1][lrow] = a4.y;
        As[lkq+2][lrow] = a4.z; As[lkq+3][lrow] = a4.w;
        Bs[lkq+0][lrow] = b4.x; Bs[lkq+1][lrow] = b4.y;
        Bs[lkq+2][lrow] = b4.z; Bs[lkq+3][lrow] = b4.w;
        __syncthreads();
        #pragma unroll
        for (int kk = 0; kk < 8; kk++) {
            float a[8], b[8];
            #pragma unroll
            for (int i = 0; i < 8; i++) a[i] = As[kk][ty*8 + i];
            #pragma unroll
            for (int j = 0; j < 8; j++) b[j] = Bs[kk][tx*8 + j];
            #pragma unroll
            for (int i = 0; i < 8; i++)
                #pragma unroll
                for (int j = 0; j < 8; j++)
                    acc[i][j] += a[i] * b[j];
        }
    }

    #pragma unroll
    for (int i = 0; i < 8; i++) {
        int m = m0 + ty*8 + i;
        #pragma unroll
        for (int j = 0; j < 8; j++) {
            int n = n0 + tx*8 + j;
            float v = acc[i][j] + bias[n];
            if (BHTD) {
                int b = m >> 11, t = m & 2047;   // T = 2048
                int h = n >> 6,  d = n & 63;     // D = 64
                C[(((size_t)(b*NHEAD + h))*SEQ + t)*HDIM + d] = v;
            } else {
                C[(size_t)m*EMBED + n] = v;
            }
        }
    }
}

// ---------------------------------------------------------------------------
// Flash attention, fp32. CTA: 64 query rows; key tiles of 64; causal.
// Threads 16x16, each thread: 4 rows x 4 cols of S / O.
// Smem: Qs,Ks d-major [64][65]; Vs row-major [64][68]; Pt [64][65].
// ---------------------------------------------------------------------------
__global__ __launch_bounds__(256) void flash_attn(const unsigned char* __restrict__ mask)
{
    extern __shared__ float sm[];
    float* Qs = sm;                 // 64*65
    float* Ks = Qs + 64*65;         // 64*65
    float* Vs = Ks + 64*65;         // 64*68
    float* Pt = Vs + 64*68;         // 64*65

    int tid = threadIdx.x;
    int tx = tid & 15, ty = tid >> 4;
    int qt = blockIdx.x, h = blockIdx.y, b = blockIdx.z;

    const float* Q  = g_q + (((size_t)(b*NHEAD + h))*SEQ + qt*64)*HDIM;
    const float* Kg = g_k + (((size_t)(b*NHEAD + h))*SEQ)*HDIM;
    const float* Vg = g_v + (((size_t)(b*NHEAD + h))*SEQ)*HDIM;
    const unsigned char* km = mask + (size_t)b*SEQ;

    // Load Q tile transposed (d-major)
    #pragma unroll
    for (int i = 0; i < 4; i++) {
        int e = tid + i*256;
        int r = e >> 4;
        int dq = (e & 15) * 4;
        float4 q4 = *reinterpret_cast<const float4*>(Q + r*HDIM + dq);
        Qs[(dq+0)*65 + r] = q4.x;
        Qs[(dq+1)*65 + r] = q4.y;
        Qs[(dq+2)*65 + r] = q4.z;
        Qs[(dq+3)*65 + r] = q4.w;
    }

    float m_i[4], l_i[4], acc[4][4];
    #pragma unroll
    for (int i = 0; i < 4; i++) {
        m_i[i] = -1e30f; l_i[i] = 0.f;
        #pragma unroll
        for (int j = 0; j < 4; j++) acc[i][j] = 0.f;
    }

    const int r0 = ty * 4, c0 = tx * 4;
    const int qbase = qt * 64;
    const float scale = 0.125f;   // 1/sqrt(64)

    for (int jt = 0; jt <= qt; jt++) {      // causal: tiles 0..qt only
        int s0 = jt * 64;
        __syncthreads();  // protect Ks/Vs/Pt from previous iteration readers
        #pragma unroll
        for (int i = 0; i < 4; i++) {
            int e = tid + i*256;
            int r = e >> 4;
            int dq = (e & 15) * 4;
            float4 k4 = *reinterpret_cast<const float4*>(Kg + (s0+r)*HDIM + dq);
            Ks[(dq+0)*65 + r] = k4.x;
            Ks[(dq+1)*65 + r] = k4.y;
            Ks[(dq+2)*65 + r] = k4.z;
            Ks[(dq+3)*65 + r] = k4.w;
            float4 v4 = *reinterpret_cast<const float4*>(Vg + (s0+r)*HDIM + dq);
            *reinterpret_cast<float4*>(Vs + r*68 + dq) = v4;
        }
        __syncthreads();

        // S = Q K^T  (4x4 per thread)
        float s[4][4];
        #pragma unroll
        for (int i = 0; i < 4; i++)
            #pragma unroll
            for (int j = 0; j < 4; j++) s[i][j] = 0.f;

        #pragma unroll 8
        for (int d = 0; d < 64; d++) {
            float a0 = Qs[d*65 + r0+0];
            float a1 = Qs[d*65 + r0+1];
            float a2 = Qs[d*65 + r0+2];
            float a3 = Qs[d*65 + r0+3];
            float b0 = Ks[d*65 + c0+0];
            float b1 = Ks[d*65 + c0+1];
            float b2 = Ks[d*65 + c0+2];
            float b3 = Ks[d*65 + c0+3];
            s[0][0] += a0*b0; s[0][1] += a0*b1; s[0][2] += a0*b2; s[0][3] += a0*b3;
            s[1][0] += a1*b0; s[1][1] += a1*b1; s[1][2] += a1*b2; s[1][3] += a1*b3;
            s[2][0] += a2*b0; s[2][1] += a2*b1; s[2][2] += a2*b2; s[2][3] += a2*b3;
            s[3][0] += a3*b0; s[3][1] += a3*b1; s[3][2] += a3*b2; s[3][3] += a3*b3;
        }

        // scale + causal + key padding mask
        #pragma unroll
        for (int i = 0; i < 4; i++) {
            int q = qbase + r0 + i;
            #pragma unroll
            for (int j = 0; j < 4; j++) {
                int kk = s0 + c0 + j;
                float v = s[i][j] * scale;
                if (kk > q || km[kk]) v = -1e30f;
                s[i][j] = v;
            }
        }

        // online softmax (row groups span 16 lanes: shfl width 16)
        #pragma unroll
        for (int i = 0; i < 4; i++) {
            float rm = fmaxf(fmaxf(s[i][0], s[i][1]), fmaxf(s[i][2], s[i][3]));
            #pragma unroll
            for (int off = 8; off > 0; off >>= 1)
                rm = fmaxf(rm, __shfl_xor_sync(0xffffffffu, rm, off, 16));
            float mn = fmaxf(m_i[i], rm);
            float corr = __expf(m_i[i] - mn);
            m_i[i] = mn;
            float rs = 0.f;
            #pragma unroll
            for (int j = 0; j < 4; j++) {
                float p = __expf(s[i][j] - mn);
                s[i][j] = p; rs += p;
            }
            #pragma unroll
            for (int off = 8; off > 0; off >>= 1)
                rs += __shfl_xor_sync(0xffffffffu, rs, off, 16);
            l_i[i] = l_i[i] * corr + rs;
            #pragma unroll
            for (int j = 0; j < 4; j++) acc[i][j] *= corr;
        }

        // stage P transposed for the PV gemm
        #pragma unroll
        for (int j = 0; j < 4; j++)
            #pragma unroll
            for (int i = 0; i < 4; i++)
                Pt[(c0+j)*65 + r0 + i] = s[i][j];
        __syncthreads();

        // O += P @ V
        #pragma unroll 8
        for (int sx = 0; sx < 64; sx++) {
            float p0 = Pt[sx*65 + r0+0];
            float p1 = Pt[sx*65 + r0+1];
            float p2 = Pt[sx*65 + r0+2];
            float p3 = Pt[sx*65 + r0+3];
            float v0 = Vs[sx*68 + c0+0];
            float v1 = Vs[sx*68 + c0+1];
            float v2 = Vs[sx*68 + c0+2];
            float v3 = Vs[sx*68 + c0+3];
            acc[0][0] += p0*v0; acc[0][1] += p0*v1; acc[0][2] += p0*v2; acc[0][3] += p0*v3;
            acc[1][0] += p1*v0; acc[1][1] += p1*v1; acc[1][2] += p1*v2; acc[1][3] += p1*v3;
            acc[2][0] += p2*v0; acc[2][1] += p2*v1; acc[2][2] += p2*v2; acc[2][3] += p2*v3;
            acc[3][0] += p3*v0; acc[3][1] += p3*v1; acc[3][2] += p3*v2; acc[3][3] += p3*v3;
        }
    }

    // epilogue: write [B,T,E]
    float* Og = g_ao + ((size_t)(b*SEQ + qbase))*EMBED + h*HDIM;
    #pragma unroll
    for (int i = 0; i < 4; i++) {
        float inv = 1.f / l_i[i];
        #pragma unroll
        for (int j = 0; j < 4; j++)
            Og[(size_t)(r0+i)*EMBED + c0 + j] = acc[i][j] * inv;
    }
}

// ---------------------------------------------------------------------------
extern "C" void kernel_launch(void* const* d_in, const int* in_sizes, int n_in,
                              void* d_out, int out_size)
{
    const float* query = (const float*)d_in[0];
    const float* key   = (const float*)d_in[1];
    const float* value = (const float*)d_in[2];
    const unsigned char* kpm = (const unsigned char*)d_in[3];
    const float* Wq = (const float*)d_in[4];
    const float* bq = (const float*)d_in[5];
    const float* Wk = (const float*)d_in[6];
    const float* bk = (const float*)d_in[7];
    const float* Wv = (const float*)d_in[8];
    const float* bv = (const float*)d_in[9];
    const float* Wo = (const float*)d_in[10];
    const float* bo = (const float*)d_in[11];
    float* out = (float*)d_out;

    float *qp, *kp, *vp, *aop;
    cudaGetSymbolAddress((void**)&qp,  g_q);
    cudaGetSymbolAddress((void**)&kp,  g_k);
    cudaGetSymbolAddress((void**)&vp,  g_v);
    cudaGetSymbolAddress((void**)&aop, g_ao);

    dim3 gproj(EMBED/128, MROWS/128);   // (8, 32)

    sgemm_bias<true><<<gproj, 256>>>(query, Wq, bq, qp);
    sgemm_bias<true><<<gproj, 256>>>(key,   Wk, bk, kp);
    sgemm_bias<true><<<gproj, 256>>>(value, Wv, bv, vp);

    const int FLASH_SMEM = (64*65 + 64*65 + 64*68 + 64*65) * (int)sizeof(float); // 67328
    cudaFuncSetAttribute(flash_attn, cudaFuncAttributeMaxDynamicSharedMemorySize, FLASH_SMEM);
    flash_attn<<<dim3(SEQ/64, NHEAD, BATCH), 256, FLASH_SMEM>>>(kpm);

    sgemm_bias<false><<<gproj, 256>>>(aop, Wo, bo, out);
}

// round 4
// speedup vs baseline: 1.4895x; 1.4895x over previous
#include <cuda_runtime.h>
#include <cstdint>

#define EMBED 1024
#define NHEAD 16
#define HDIM  64
#define BATCH 2
#define SEQ   2048
#define MROWS (BATCH*SEQ)   // 4096

// Scratch (allocation-free rule: __device__ globals)
__device__ float g_q[BATCH*NHEAD*SEQ*HDIM];   // [B,H,T,D]
__device__ float g_k[BATCH*NHEAD*SEQ*HDIM];
__device__ float g_v[BATCH*NHEAD*SEQ*HDIM];
__device__ float g_ao[MROWS*EMBED];           // attention out, [B,T,E]

// ---------------------------------------------------------------------------
// TF32 tensor-core GEMM: C = A @ W^T + bias.
// A:[M,K=1024] row-major, W:[N,K] row-major (so W^T is col-major -> mma row.col).
// Block 128x128, BK=16, 256 threads = 8 warps (4m x 2n), warp tile 32x64,
// per warp 2(m16) x 8(n8) mma tiles of m16n8k8.
// Smem layout [row][20] (stride 20 words) -> conflict-free fragment LDS.
// ---------------------------------------------------------------------------
__device__ __forceinline__ uint32_t f2tf32(float x) {
    uint32_t r;
    asm("cvt.rna.tf32.f32 %0, %1;" : "=r"(r) : "f"(x));
    return r;
}

__device__ __forceinline__ void mma_tf32(float* c, const uint32_t* a,
                                         uint32_t b0, uint32_t b1) {
    asm volatile(
        "mma.sync.aligned.m16n8k8.row.col.f32.tf32.tf32.f32 "
        "{%0,%1,%2,%3}, {%4,%5,%6,%7}, {%8,%9}, {%0,%1,%2,%3};"
        : "+f"(c[0]), "+f"(c[1]), "+f"(c[2]), "+f"(c[3])
        : "r"(a[0]), "r"(a[1]), "r"(a[2]), "r"(a[3]), "r"(b0), "r"(b1));
}

template<bool BHTD>
__global__ __launch_bounds__(256) void gemm_tf32(
    const float* __restrict__ A, const float* __restrict__ W,
    const float* __restrict__ bias, float* __restrict__ C)
{
    const int K = EMBED;
    __shared__ uint32_t As[128][20];
    __shared__ uint32_t Ws[128][20];

    int tid  = threadIdx.x;
    int lane = tid & 31;
    int warp = tid >> 5;
    int wm = warp >> 1, wn = warp & 1;
    int m0w = wm * 32, n0w = wn * 64;
    int m0 = blockIdx.y * 128;
    int n0 = blockIdx.x * 128;

    float c[2][8][4];
    #pragma unroll
    for (int mi = 0; mi < 2; mi++)
        #pragma unroll
        for (int ni = 0; ni < 8; ni++)
            #pragma unroll
            for (int q = 0; q < 4; q++) c[mi][ni][q] = 0.f;

    for (int k0 = 0; k0 < K; k0 += 16) {
        __syncthreads();
        #pragma unroll
        for (int s = 0; s < 2; s++) {
            int i  = tid + s * 256;
            int r  = i >> 2;
            int kq = (i & 3) << 2;
            float4 a4 = *reinterpret_cast<const float4*>(A + (size_t)(m0 + r) * K + k0 + kq);
            uint4 ta = make_uint4(f2tf32(a4.x), f2tf32(a4.y), f2tf32(a4.z), f2tf32(a4.w));
            *reinterpret_cast<uint4*>(&As[r][kq]) = ta;
            float4 w4 = *reinterpret_cast<const float4*>(W + (size_t)(n0 + r) * K + k0 + kq);
            uint4 tw = make_uint4(f2tf32(w4.x), f2tf32(w4.y), f2tf32(w4.z), f2tf32(w4.w));
            *reinterpret_cast<uint4*>(&Ws[r][kq]) = tw;
        }
        __syncthreads();

        #pragma unroll
        for (int kk = 0; kk < 16; kk += 8) {
            int kb = kk + (lane & 3);
            uint32_t a[2][4];
            #pragma unroll
            for (int mi = 0; mi < 2; mi++) {
                int r = m0w + mi * 16 + (lane >> 2);
                a[mi][0] = As[r][kb];
                a[mi][1] = As[r + 8][kb];
                a[mi][2] = As[r][kb + 4];
                a[mi][3] = As[r + 8][kb + 4];
            }
            #pragma unroll
            for (int ni = 0; ni < 8; ni++) {
                int rn = n0w + ni * 8 + (lane >> 2);
                uint32_t b0 = Ws[rn][kb];
                uint32_t b1 = Ws[rn][kb + 4];
                mma_tf32(c[0][ni], a[0], b0, b1);
                mma_tf32(c[1][ni], a[1], b0, b1);
            }
        }
    }

    // epilogue
    #pragma unroll
    for (int mi = 0; mi < 2; mi++) {
        int rbase = m0 + m0w + mi * 16 + (lane >> 2);
        #pragma unroll
        for (int ni = 0; ni < 8; ni++) {
            int col = n0 + n0w + ni * 8 + 2 * (lane & 3);
            float bv0 = bias[col], bv1 = bias[col + 1];
            #pragma unroll
            for (int half = 0; half < 2; half++) {
                int m = rbase + half * 8;
                float v0 = c[mi][ni][half * 2 + 0] + bv0;
                float v1 = c[mi][ni][half * 2 + 1] + bv1;
                if (BHTD) {
                    int b = m >> 11, t = m & 2047;
                    int h = col >> 6, d = col & 63;
                    size_t base = (((size_t)(b * NHEAD + h)) * SEQ + t) * HDIM + d;
                    C[base]     = v0;
                    C[base + 1] = v1;   // col even -> d, d+1 stay within one head
                } else {
                    C[(size_t)m * EMBED + col]     = v0;
                    C[(size_t)m * EMBED + col + 1] = v1;
                }
            }
        }
    }
}

// ---------------------------------------------------------------------------
// Flash attention, fp32. CTA: 64 query rows; key tiles of 64; causal.
// ---------------------------------------------------------------------------
__global__ __launch_bounds__(256) void flash_attn(const unsigned char* __restrict__ mask)
{
    extern __shared__ float sm[];
    float* Qs = sm;                 // 64*65
    float* Ks = Qs + 64*65;         // 64*65
    float* Vs = Ks + 64*65;         // 64*68
    float* Pt = Vs + 64*68;         // 64*65

    int tid = threadIdx.x;
    int tx = tid & 15, ty = tid >> 4;
    int qt = blockIdx.x, h = blockIdx.y, b = blockIdx.z;

    const float* Q  = g_q + (((size_t)(b*NHEAD + h))*SEQ + qt*64)*HDIM;
    const float* Kg = g_k + (((size_t)(b*NHEAD + h))*SEQ)*HDIM;
    const float* Vg = g_v + (((size_t)(b*NHEAD + h))*SEQ)*HDIM;
    const unsigned char* km = mask + (size_t)b*SEQ;

    #pragma unroll
    for (int i = 0; i < 4; i++) {
        int e = tid + i*256;
        int r = e >> 4;
        int dq = (e & 15) * 4;
        float4 q4 = *reinterpret_cast<const float4*>(Q + r*HDIM + dq);
        Qs[(dq+0)*65 + r] = q4.x;
        Qs[(dq+1)*65 + r] = q4.y;
        Qs[(dq+2)*65 + r] = q4.z;
        Qs[(dq+3)*65 + r] = q4.w;
    }

    float m_i[4], l_i[4], acc[4][4];
    #pragma unroll
    for (int i = 0; i < 4; i++) {
        m_i[i] = -1e30f; l_i[i] = 0.f;
        #pragma unroll
        for (int j = 0; j < 4; j++) acc[i][j] = 0.f;
    }

    const int r0 = ty * 4, c0 = tx * 4;
    const int qbase = qt * 64;
    const float scale = 0.125f;

    for (int jt = 0; jt <= qt; jt++) {
        int s0 = jt * 64;
        __syncthreads();
        #pragma unroll
        for (int i = 0; i < 4; i++) {
            int e = tid + i*256;
            int r = e >> 4;
            int dq = (e & 15) * 4;
            float4 k4 = *reinterpret_cast<const float4*>(Kg + (s0+r)*HDIM + dq);
            Ks[(dq+0)*65 + r] = k4.x;
            Ks[(dq+1)*65 + r] = k4.y;
            Ks[(dq+2)*65 + r] = k4.z;
            Ks[(dq+3)*65 + r] = k4.w;
            float4 v4 = *reinterpret_cast<const float4*>(Vg + (s0+r)*HDIM + dq);
            *reinterpret_cast<float4*>(Vs + r*68 + dq) = v4;
        }
        __syncthreads();

        float s[4][4];
        #pragma unroll
        for (int i = 0; i < 4; i++)
            #pragma unroll
            for (int j = 0; j < 4; j++) s[i][j] = 0.f;

        #pragma unroll 8
        for (int d = 0; d < 64; d++) {
            float a0 = Qs[d*65 + r0+0];
            float a1 = Qs[d*65 + r0+1];
            float a2 = Qs[d*65 + r0+2];
            float a3 = Qs[d*65 + r0+3];
            float b0 = Ks[d*65 + c0+0];
            float b1 = Ks[d*65 + c0+1];
            float b2 = Ks[d*65 + c0+2];
            float b3 = Ks[d*65 + c0+3];
            s[0][0] += a0*b0; s[0][1] += a0*b1; s[0][2] += a0*b2; s[0][3] += a0*b3;
            s[1][0] += a1*b0; s[1][1] += a1*b1; s[1][2] += a1*b2; s[1][3] += a1*b3;
            s[2][0] += a2*b0; s[2][1] += a2*b1; s[2][2] += a2*b2; s[2][3] += a2*b3;
            s[3][0] += a3*b0; s[3][1] += a3*b1; s[3][2] += a3*b2; s[3][3] += a3*b3;
        }

        #pragma unroll
        for (int i = 0; i < 4; i++) {
            int q = qbase + r0 + i;
            #pragma unroll
            for (int j = 0; j < 4; j++) {
                int kk = s0 + c0 + j;
                float v = s[i][j] * scale;
                if (kk > q || km[kk]) v = -1e30f;
                s[i][j] = v;
            }
        }

        #pragma unroll
        for (int i = 0; i < 4; i++) {
            float rm = fmaxf(fmaxf(s[i][0], s[i][1]), fmaxf(s[i][2], s[i][3]));
            #pragma unroll
            for (int off = 8; off > 0; off >>= 1)
                rm = fmaxf(rm, __shfl_xor_sync(0xffffffffu, rm, off, 16));
            float mn = fmaxf(m_i[i], rm);
            float corr = __expf(m_i[i] - mn);
            m_i[i] = mn;
            float rs = 0.f;
            #pragma unroll
            for (int j = 0; j < 4; j++) {
                float p = __expf(s[i][j] - mn);
                s[i][j] = p; rs += p;
            }
            #pragma unroll
            for (int off = 8; off > 0; off >>= 1)
                rs += __shfl_xor_sync(0xffffffffu, rs, off, 16);
            l_i[i] = l_i[i] * corr + rs;
            #pragma unroll
            for (int j = 0; j < 4; j++) acc[i][j] *= corr;
        }

        #pragma unroll
        for (int j = 0; j < 4; j++)
            #pragma unroll
            for (int i = 0; i < 4; i++)
                Pt[(c0+j)*65 + r0 + i] = s[i][j];
        __syncthreads();

        #pragma unroll 8
        for (int sx = 0; sx < 64; sx++) {
            float p0 = Pt[sx*65 + r0+0];
            float p1 = Pt[sx*65 + r0+1];
            float p2 = Pt[sx*65 + r0+2];
            float p3 = Pt[sx*65 + r0+3];
            float v0 = Vs[sx*68 + c0+0];
            float v1 = Vs[sx*68 + c0+1];
            float v2 = Vs[sx*68 + c0+2];
            float v3 = Vs[sx*68 + c0+3];
            acc[0][0] += p0*v0; acc[0][1] += p0*v1; acc[0][2] += p0*v2; acc[0][3] += p0*v3;
            acc[1][0] += p1*v0; acc[1][1] += p1*v1; acc[1][2] += p1*v2; acc[1][3] += p1*v3;
            acc[2][0] += p2*v0; acc[2][1] += p2*v1; acc[2][2] += p2*v2; acc[2][3] += p2*v3;
            acc[3][0] += p3*v0; acc[3][1] += p3*v1; acc[3][2] += p3*v2; acc[3][3] += p3*v3;
        }
    }

    float* Og = g_ao + ((size_t)(b*SEQ + qbase))*EMBED + h*HDIM;
    #pragma unroll
    for (int i = 0; i < 4; i++) {
        float inv = 1.f / l_i[i];
        #pragma unroll
        for (int j = 0; j < 4; j++)
            Og[(size_t)(r0+i)*EMBED + c0 + j] = acc[i][j] * inv;
    }
}

// ---------------------------------------------------------------------------
extern "C" void kernel_launch(void* const* d_in, const int* in_sizes, int n_in,
                              void* d_out, int out_size)
{
    const float* query = (const float*)d_in[0];
    const float* key   = (const float*)d_in[1];
    const float* value = (const float*)d_in[2];
    const unsigned char* kpm = (const unsigned char*)d_in[3];
    const float* Wq = (const float*)d_in[4];
    const float* bq = (const float*)d_in[5];
    const float* Wk = (const float*)d_in[6];
    const float* bk = (const float*)d_in[7];
    const float* Wv = (const float*)d_in[8];
    const float* bv = (const float*)d_in[9];
    const float* Wo = (const float*)d_in[10];
    const float* bo = (const float*)d_in[11];
    float* out = (float*)d_out;

    float *qp, *kp, *vp, *aop;
    cudaGetSymbolAddress((void**)&qp,  g_q);
    cudaGetSymbolAddress((void**)&kp,  g_k);
    cudaGetSymbolAddress((void**)&vp,  g_v);
    cudaGetSymbolAddress((void**)&aop, g_ao);

    dim3 gproj(EMBED/128, MROWS/128);   // (8, 32)

    gemm_tf32<true><<<gproj, 256>>>(query, Wq, bq, qp);
    gemm_tf32<true><<<gproj, 256>>>(key,   Wk, bk, kp);
    gemm_tf32<true><<<gproj, 256>>>(value, Wv, bv, vp);

    const int FLASH_SMEM = (64*65 + 64*65 + 64*68 + 64*65) * (int)sizeof(float); // 67328
    cudaFuncSetAttribute(flash_attn, cudaFuncAttributeMaxDynamicSharedMemorySize, FLASH_SMEM);
    flash_attn<<<dim3(SEQ/64, NHEAD, BATCH), 256, FLASH_SMEM>>>(kpm);

    gemm_tf32<false><<<gproj, 256>>>(aop, Wo, bo, out);
}

// round 5
// speedup vs baseline: 2.2960x; 1.5414x over previous
#include <cuda_runtime.h>
#include <cuda_bf16.h>
#include <cstdint>

#define EMBED 1024
#define NHEAD 16
#define HDIM  64
#define BATCH 2
#define SEQ   2048
#define MROWS (BATCH*SEQ)   // 4096

// Scratch (allocation-free rule: __device__ globals)
__device__ float g_q[BATCH*NHEAD*SEQ*HDIM];   // [B,H,T,D]
__device__ float g_k[BATCH*NHEAD*SEQ*HDIM];
__device__ float g_v[BATCH*NHEAD*SEQ*HDIM];
__device__ float g_ao[MROWS*EMBED];           // attention out, [B,T,E]

// ---------------------------------------------------------------------------
// TF32 tensor-core GEMM: C = A @ W^T + bias.  (unchanged from R4 — passing)
// ---------------------------------------------------------------------------
__device__ __forceinline__ uint32_t f2tf32(float x) {
    uint32_t r;
    asm("cvt.rna.tf32.f32 %0, %1;" : "=r"(r) : "f"(x));
    return r;
}

__device__ __forceinline__ void mma_tf32(float* c, const uint32_t* a,
                                         uint32_t b0, uint32_t b1) {
    asm volatile(
        "mma.sync.aligned.m16n8k8.row.col.f32.tf32.tf32.f32 "
        "{%0,%1,%2,%3}, {%4,%5,%6,%7}, {%8,%9}, {%0,%1,%2,%3};"
        : "+f"(c[0]), "+f"(c[1]), "+f"(c[2]), "+f"(c[3])
        : "r"(a[0]), "r"(a[1]), "r"(a[2]), "r"(a[3]), "r"(b0), "r"(b1));
}

template<bool BHTD>
__global__ __launch_bounds__(256) void gemm_tf32(
    const float* __restrict__ A, const float* __restrict__ W,
    const float* __restrict__ bias, float* __restrict__ C)
{
    const int K = EMBED;
    __shared__ uint32_t As[128][20];
    __shared__ uint32_t Ws[128][20];

    int tid  = threadIdx.x;
    int lane = tid & 31;
    int warp = tid >> 5;
    int wm = warp >> 1, wn = warp & 1;
    int m0w = wm * 32, n0w = wn * 64;
    int m0 = blockIdx.y * 128;
    int n0 = blockIdx.x * 128;

    float c[2][8][4];
    #pragma unroll
    for (int mi = 0; mi < 2; mi++)
        #pragma unroll
        for (int ni = 0; ni < 8; ni++)
            #pragma unroll
            for (int q = 0; q < 4; q++) c[mi][ni][q] = 0.f;

    for (int k0 = 0; k0 < K; k0 += 16) {
        __syncthreads();
        #pragma unroll
        for (int s = 0; s < 2; s++) {
            int i  = tid + s * 256;
            int r  = i >> 2;
            int kq = (i & 3) << 2;
            float4 a4 = *reinterpret_cast<const float4*>(A + (size_t)(m0 + r) * K + k0 + kq);
            uint4 ta = make_uint4(f2tf32(a4.x), f2tf32(a4.y), f2tf32(a4.z), f2tf32(a4.w));
            *reinterpret_cast<uint4*>(&As[r][kq]) = ta;
            float4 w4 = *reinterpret_cast<const float4*>(W + (size_t)(n0 + r) * K + k0 + kq);
            uint4 tw = make_uint4(f2tf32(w4.x), f2tf32(w4.y), f2tf32(w4.z), f2tf32(w4.w));
            *reinterpret_cast<uint4*>(&Ws[r][kq]) = tw;
        }
        __syncthreads();

        #pragma unroll
        for (int kk = 0; kk < 16; kk += 8) {
            int kb = kk + (lane & 3);
            uint32_t a[2][4];
            #pragma unroll
            for (int mi = 0; mi < 2; mi++) {
                int r = m0w + mi * 16 + (lane >> 2);
                a[mi][0] = As[r][kb];
                a[mi][1] = As[r + 8][kb];
                a[mi][2] = As[r][kb + 4];
                a[mi][3] = As[r + 8][kb + 4];
            }
            #pragma unroll
            for (int ni = 0; ni < 8; ni++) {
                int rn = n0w + ni * 8 + (lane >> 2);
                uint32_t b0 = Ws[rn][kb];
                uint32_t b1 = Ws[rn][kb + 4];
                mma_tf32(c[0][ni], a[0], b0, b1);
                mma_tf32(c[1][ni], a[1], b0, b1);
            }
        }
    }

    #pragma unroll
    for (int mi = 0; mi < 2; mi++) {
        int rbase = m0 + m0w + mi * 16 + (lane >> 2);
        #pragma unroll
        for (int ni = 0; ni < 8; ni++) {
            int col = n0 + n0w + ni * 8 + 2 * (lane & 3);
            float bv0 = bias[col], bv1 = bias[col + 1];
            #pragma unroll
            for (int half = 0; half < 2; half++) {
                int m = rbase + half * 8;
                float v0 = c[mi][ni][half * 2 + 0] + bv0;
                float v1 = c[mi][ni][half * 2 + 1] + bv1;
                if (BHTD) {
                    int b = m >> 11, t = m & 2047;
                    int h = col >> 6, d = col & 63;
                    size_t base = (((size_t)(b * NHEAD + h)) * SEQ + t) * HDIM + d;
                    C[base]     = v0;
                    C[base + 1] = v1;
                } else {
                    C[(size_t)m * EMBED + col]     = v0;
                    C[(size_t)m * EMBED + col + 1] = v1;
                }
            }
        }
    }
}

// ---------------------------------------------------------------------------
// Flash attention via bf16 split mma (hi+lo, 3 terms ~ fp32 accuracy).
// CTA: 128 q-rows, 8 warps (m16 each). Key tiles of 64. Causal: 2qt+2 tiles.
// Smem: Q/K row-major [row][d] pitch 72 bf16, V transposed [d][s] pitch 72.
// ---------------------------------------------------------------------------
__device__ __forceinline__ void mma_bf16(float* c, const uint32_t* a,
                                         uint32_t b0, uint32_t b1) {
    asm volatile(
        "mma.sync.aligned.m16n8k16.row.col.f32.bf16.bf16.f32 "
        "{%0,%1,%2,%3}, {%4,%5,%6,%7}, {%8,%9}, {%0,%1,%2,%3};"
        : "+f"(c[0]), "+f"(c[1]), "+f"(c[2]), "+f"(c[3])
        : "r"(a[0]), "r"(a[1]), "r"(a[2]), "r"(a[3]), "r"(b0), "r"(b1));
}

__device__ __forceinline__ void pack2(float x, float y, uint32_t& hi, uint32_t& lo) {
    __nv_bfloat16 hx = __float2bfloat16(x), hy = __float2bfloat16(y);
    __nv_bfloat162 h2; h2.x = hx; h2.y = hy;
    hi = *reinterpret_cast<uint32_t*>(&h2);
    __nv_bfloat162 l2;
    l2.x = __float2bfloat16(x - __bfloat162float(hx));
    l2.y = __float2bfloat16(y - __bfloat162float(hy));
    lo = *reinterpret_cast<uint32_t*>(&l2);
}

#define FPITCH 72   // bf16 pitch: 36 words -> banks (4n+c), conflict-free frags

__global__ __launch_bounds__(256, 1) void flash_attn_mma(const unsigned char* __restrict__ mask)
{
    extern __shared__ __align__(16) char smraw[];
    __nv_bfloat16* sQh = (__nv_bfloat16*)smraw;
    __nv_bfloat16* sQl = sQh + 128*FPITCH;
    __nv_bfloat16* sKh = sQl + 128*FPITCH;
    __nv_bfloat16* sKl = sKh + 64*FPITCH;
    __nv_bfloat16* sVh = sKl + 64*FPITCH;     // transposed: [d][s]
    __nv_bfloat16* sVl = sVh + 64*FPITCH;
    float* mfs = (float*)(sVl + 64*FPITCH);   // 64 floats

    int tid  = threadIdx.x;
    int lane = tid & 31, warp = tid >> 5;
    int grp  = lane >> 2, thr4 = lane & 3;
    int qt = (int)gridDim.x - 1 - (int)blockIdx.x;   // heavy tiles first
    int h = blockIdx.y, b = blockIdx.z;
    int qbase = qt * 128;

    const float* Qg = g_q + (((size_t)(b*NHEAD + h))*SEQ + qbase)*HDIM;
    const float* Kg = g_k + ((size_t)(b*NHEAD + h))*SEQ*HDIM;
    const float* Vg = g_v + ((size_t)(b*NHEAD + h))*SEQ*HDIM;
    const unsigned char* km = mask + (size_t)b*SEQ;

    // ---- stage Q (128x64) as bf16 hi/lo, row-major ----
    #pragma unroll
    for (int i = 0; i < 8; i++) {
        int e = tid + i*256;          // 0..2047
        int r = e >> 4, c4 = (e & 15) << 2;
        float4 q = *reinterpret_cast<const float4*>(Qg + r*HDIM + c4);
        __nv_bfloat16* hp = sQh + r*FPITCH + c4;
        __nv_bfloat16* lp = sQl + r*FPITCH + c4;
        __nv_bfloat16 h0 = __float2bfloat16(q.x), h1 = __float2bfloat16(q.y),
                      h2 = __float2bfloat16(q.z), h3 = __float2bfloat16(q.w);
        hp[0]=h0; hp[1]=h1; hp[2]=h2; hp[3]=h3;
        lp[0]=__float2bfloat16(q.x-__bfloat162float(h0));
        lp[1]=__float2bfloat16(q.y-__bfloat162float(h1));
        lp[2]=__float2bfloat16(q.z-__bfloat162float(h2));
        lp[3]=__float2bfloat16(q.w-__bfloat162float(h3));
    }
    __syncthreads();

    // ---- preload Q fragments (A frags, m16k16 x 4 ksteps, hi+lo) ----
    uint32_t qh[4][4], ql[4][4];
    {
        int rl = warp*16 + grp;
        #pragma unroll
        for (int ks = 0; ks < 4; ks++) {
            int cc = thr4*2 + ks*16;
            qh[ks][0] = *(const uint32_t*)(sQh + rl*FPITCH + cc);
            qh[ks][1] = *(const uint32_t*)(sQh + (rl+8)*FPITCH + cc);
            qh[ks][2] = *(const uint32_t*)(sQh + rl*FPITCH + cc + 8);
            qh[ks][3] = *(const uint32_t*)(sQh + (rl+8)*FPITCH + cc + 8);
            ql[ks][0] = *(const uint32_t*)(sQl + rl*FPITCH + cc);
            ql[ks][1] = *(const uint32_t*)(sQl + (rl+8)*FPITCH + cc);
            ql[ks][2] = *(const uint32_t*)(sQl + rl*FPITCH + cc + 8);
            ql[ks][3] = *(const uint32_t*)(sQl + (rl+8)*FPITCH + cc + 8);
        }
    }

    int row0 = qbase + warp*16 + grp;
    int row1 = row0 + 8;

    float m0 = -1e30f, m1 = -1e30f, l0 = 0.f, l1 = 0.f;
    float o[8][4];
    #pragma unroll
    for (int j = 0; j < 8; j++)
        #pragma unroll
        for (int q = 0; q < 4; q++) o[j][q] = 0.f;

    const int ntiles = 2*qt + 2;
    for (int jt = 0; jt < ntiles; jt++) {
        int s0 = jt * 64;
        __syncthreads();
        // load K/V tile (64x64), split; V stored transposed
        #pragma unroll
        for (int i = 0; i < 4; i++) {
            int e = tid + i*256;          // 0..1023
            int r = e >> 4, c4 = (e & 15) << 2;
            float4 kk = *reinterpret_cast<const float4*>(Kg + (size_t)(s0+r)*HDIM + c4);
            __nv_bfloat16* hp = sKh + r*FPITCH + c4;
            __nv_bfloat16* lp = sKl + r*FPITCH + c4;
            __nv_bfloat16 h0 = __float2bfloat16(kk.x), h1 = __float2bfloat16(kk.y),
                          h2 = __float2bfloat16(kk.z), h3 = __float2bfloat16(kk.w);
            hp[0]=h0; hp[1]=h1; hp[2]=h2; hp[3]=h3;
            lp[0]=__float2bfloat16(kk.x-__bfloat162float(h0));
            lp[1]=__float2bfloat16(kk.y-__bfloat162float(h1));
            lp[2]=__float2bfloat16(kk.z-__bfloat162float(h2));
            lp[3]=__float2bfloat16(kk.w-__bfloat162float(h3));

            float4 vv = *reinterpret_cast<const float4*>(Vg + (size_t)(s0+r)*HDIM + c4);
            float vf[4] = {vv.x, vv.y, vv.z, vv.w};
            #pragma unroll
            for (int u = 0; u < 4; u++) {
                __nv_bfloat16 vh = __float2bfloat16(vf[u]);
                sVh[(c4+u)*FPITCH + r] = vh;
                sVl[(c4+u)*FPITCH + r] = __float2bfloat16(vf[u]-__bfloat162float(vh));
            }
        }
        if (tid < 64) mfs[tid] = km[s0 + tid] ? -1e30f : 0.0f;
        __syncthreads();

        // ---- S = Q K^T (split bf16, 3 terms) ----
        float s[8][4];
        #pragma unroll
        for (int j = 0; j < 8; j++)
            #pragma unroll
            for (int q = 0; q < 4; q++) s[j][q] = 0.f;

        #pragma unroll
        for (int ks = 0; ks < 4; ks++) {
            int cc = thr4*2 + ks*16;
            #pragma unroll
            for (int j = 0; j < 8; j++) {
                int n = j*8 + grp;
                uint32_t bh0 = *(const uint32_t*)(sKh + n*FPITCH + cc);
                uint32_t bh1 = *(const uint32_t*)(sKh + n*FPITCH + cc + 8);
                uint32_t bl0 = *(const uint32_t*)(sKl + n*FPITCH + cc);
                uint32_t bl1 = *(const uint32_t*)(sKl + n*FPITCH + cc + 8);
                mma_bf16(s[j], qh[ks], bh0, bh1);
                mma_bf16(s[j], qh[ks], bl0, bl1);
                mma_bf16(s[j], ql[ks], bh0, bh1);
            }
        }

        // ---- scale + masks + online softmax ----
        bool diag = (jt >= 2*qt);
        float nm0 = m0, nm1 = m1;
        #pragma unroll
        for (int j = 0; j < 8; j++) {
            int cb = 8*j + 2*thr4;
            float f0 = mfs[cb], f1 = mfs[cb+1];
            float v00 = fmaf(s[j][0], 0.125f, f0);
            float v01 = fmaf(s[j][1], 0.125f, f1);
            float v10 = fmaf(s[j][2], 0.125f, f0);
            float v11 = fmaf(s[j][3], 0.125f, f1);
            if (diag) {
                int ca = s0 + cb;
                if (ca     > row0) v00 = -1e30f;
                if (ca + 1 > row0) v01 = -1e30f;
                if (ca     > row1) v10 = -1e30f;
                if (ca + 1 > row1) v11 = -1e30f;
            }
            s[j][0] = v00; s[j][1] = v01; s[j][2] = v10; s[j][3] = v11;
            nm0 = fmaxf(nm0, fmaxf(v00, v01));
            nm1 = fmaxf(nm1, fmaxf(v10, v11));
        }
        nm0 = fmaxf(nm0, __shfl_xor_sync(0xffffffffu, nm0, 1));
        nm0 = fmaxf(nm0, __shfl_xor_sync(0xffffffffu, nm0, 2));
        nm1 = fmaxf(nm1, __shfl_xor_sync(0xffffffffu, nm1, 1));
        nm1 = fmaxf(nm1, __shfl_xor_sync(0xffffffffu, nm1, 2));

        float c0 = __expf(m0 - nm0), c1 = __expf(m1 - nm1);
        m0 = nm0; m1 = nm1;

        float ls0 = 0.f, ls1 = 0.f;
        #pragma unroll
        for (int j = 0; j < 8; j++) {
            s[j][0] = __expf(s[j][0] - m0);
            s[j][1] = __expf(s[j][1] - m0);
            s[j][2] = __expf(s[j][2] - m1);
            s[j][3] = __expf(s[j][3] - m1);
            ls0 += s[j][0] + s[j][1];
            ls1 += s[j][2] + s[j][3];
        }
        ls0 += __shfl_xor_sync(0xffffffffu, ls0, 1);
        ls0 += __shfl_xor_sync(0xffffffffu, ls0, 2);
        ls1 += __shfl_xor_sync(0xffffffffu, ls1, 1);
        ls1 += __shfl_xor_sync(0xffffffffu, ls1, 2);
        l0 = l0*c0 + ls0;
        l1 = l1*c1 + ls1;

        #pragma unroll
        for (int j = 0; j < 8; j++) {
            o[j][0] *= c0; o[j][1] *= c0;
            o[j][2] *= c1; o[j][3] *= c1;
        }

        // ---- O += P V (split bf16) ----
        #pragma unroll
        for (int ks = 0; ks < 4; ks++) {
            uint32_t ph[4], pl[4];
            float* sa = s[2*ks];
            float* sb = s[2*ks + 1];
            pack2(sa[0], sa[1], ph[0], pl[0]);
            pack2(sa[2], sa[3], ph[1], pl[1]);
            pack2(sb[0], sb[1], ph[2], pl[2]);
            pack2(sb[2], sb[3], ph[3], pl[3]);
            int cc = thr4*2 + ks*16;
            #pragma unroll
            for (int j = 0; j < 8; j++) {
                int n = j*8 + grp;       // d index
                uint32_t vh0 = *(const uint32_t*)(sVh + n*FPITCH + cc);
                uint32_t vh1 = *(const uint32_t*)(sVh + n*FPITCH + cc + 8);
                uint32_t vl0 = *(const uint32_t*)(sVl + n*FPITCH + cc);
                uint32_t vl1 = *(const uint32_t*)(sVl + n*FPITCH + cc + 8);
                mma_bf16(o[j], ph, vh0, vh1);
                mma_bf16(o[j], ph, vl0, vl1);
                mma_bf16(o[j], pl, vh0, vh1);
            }
        }
    }

    // ---- epilogue: [B,T,E] ----
    float inv0 = 1.f / l0, inv1 = 1.f / l1;
    float* O0 = g_ao + ((size_t)(b*SEQ) + row0)*EMBED + h*HDIM;
    float* O1 = g_ao + ((size_t)(b*SEQ) + row1)*EMBED + h*HDIM;
    #pragma unroll
    for (int j = 0; j < 8; j++) {
        int col = 8*j + 2*thr4;
        float2 r0 = make_float2(o[j][0]*inv0, o[j][1]*inv0);
        float2 r1 = make_float2(o[j][2]*inv1, o[j][3]*inv1);
        *reinterpret_cast<float2*>(O0 + col) = r0;
        *reinterpret_cast<float2*>(O1 + col) = r1;
    }
}

// ---------------------------------------------------------------------------
extern "C" void kernel_launch(void* const* d_in, const int* in_sizes, int n_in,
                              void* d_out, int out_size)
{
    const float* query = (const float*)d_in[0];
    const float* key   = (const float*)d_in[1];
    const float* value = (const float*)d_in[2];
    const unsigned char* kpm = (const unsigned char*)d_in[3];
    const float* Wq = (const float*)d_in[4];
    const float* bq = (const float*)d_in[5];
    const float* Wk = (const float*)d_in[6];
    const float* bk = (const float*)d_in[7];
    const float* Wv = (const float*)d_in[8];
    const float* bv = (const float*)d_in[9];
    const float* Wo = (const float*)d_in[10];
    const float* bo = (const float*)d_in[11];
    float* out = (float*)d_out;

    float *qp, *kp, *vp, *aop;
    cudaGetSymbolAddress((void**)&qp,  g_q);
    cudaGetSymbolAddress((void**)&kp,  g_k);
    cudaGetSymbolAddress((void**)&vp,  g_v);
    cudaGetSymbolAddress((void**)&aop, g_ao);

    dim3 gproj(EMBED/128, MROWS/128);   // (8, 32)

    gemm_tf32<true><<<gproj, 256>>>(query, Wq, bq, qp);
    gemm_tf32<true><<<gproj, 256>>>(key,   Wk, bk, kp);
    gemm_tf32<true><<<gproj, 256>>>(value, Wv, bv, vp);

    // smem: (128 + 128 + 64*4) * 72 bf16 * 2B + 64 * 4B
    const int FLASH_SMEM = (128*2 + 64*4) * FPITCH * 2 + 64 * 4;  // 73984
    cudaFuncSetAttribute(flash_attn_mma, cudaFuncAttributeMaxDynamicSharedMemorySize, FLASH_SMEM);
    flash_attn_mma<<<dim3(SEQ/128, NHEAD, BATCH), 256, FLASH_SMEM>>>(kpm);

    gemm_tf32<false><<<gproj, 256>>>(aop, Wo, bo, out);
}

// round 7
// speedup vs baseline: 2.6279x; 1.1446x over previous
#include <cuda_runtime.h>
#include <cuda_bf16.h>
#include <cstdint>

#define EMBED 1024
#define NHEAD 16
#define HDIM  64
#define BATCH 2
#define SEQ   2048
#define MROWS (BATCH*SEQ)   // 4096

__device__ float g_q[BATCH*NHEAD*SEQ*HDIM];   // [B,H,T,D]
__device__ float g_k[BATCH*NHEAD*SEQ*HDIM];
__device__ float g_v[BATCH*NHEAD*SEQ*HDIM];
__device__ float g_ao[MROWS*EMBED];           // attention out, [B,T,E]

// ---------------------------------------------------------------------------
// TF32 tensor-core GEMM, register-prefetch pipelined.
// ---------------------------------------------------------------------------
__device__ __forceinline__ uint32_t f2tf32(float x) {
    uint32_t r;
    asm("cvt.rna.tf32.f32 %0, %1;" : "=r"(r) : "f"(x));
    return r;
}

__device__ __forceinline__ void mma_tf32(float* c, const uint32_t* a,
                                         uint32_t b0, uint32_t b1) {
    asm volatile(
        "mma.sync.aligned.m16n8k8.row.col.f32.tf32.tf32.f32 "
        "{%0,%1,%2,%3}, {%4,%5,%6,%7}, {%8,%9}, {%0,%1,%2,%3};"
        : "+f"(c[0]), "+f"(c[1]), "+f"(c[2]), "+f"(c[3])
        : "r"(a[0]), "r"(a[1]), "r"(a[2]), "r"(a[3]), "r"(b0), "r"(b1));
}

// Shared GEMM body. BHTD: scatter to [B,H,T,D].
template<bool BHTD>
__device__ __forceinline__ void gemm_body(
    const float* __restrict__ A, const float* __restrict__ W,
    const float* __restrict__ bias, float* __restrict__ C,
    int m0, int n0)
{
    const int K = EMBED;
    __shared__ uint32_t As[128][20];
    __shared__ uint32_t Ws[128][20];

    int tid  = threadIdx.x;
    int lane = tid & 31;
    int warp = tid >> 5;
    int wm = warp >> 1, wn = warp & 1;
    int m0w = wm * 32, n0w = wn * 64;

    float c[2][8][4];
    #pragma unroll
    for (int mi = 0; mi < 2; mi++)
        #pragma unroll
        for (int ni = 0; ni < 8; ni++)
            #pragma unroll
            for (int q = 0; q < 4; q++) c[mi][ni][q] = 0.f;

    // per-thread load coords (two chunks: i = tid, tid+256)
    int r0c = tid >> 2,           kq0 = (tid & 3) << 2;
    int r1c = (tid + 256) >> 2,   kq1 = kq0;            // (tid+256)&3 == tid&3

    const float* Ap0 = A + (size_t)(m0 + r0c) * K + kq0;
    const float* Ap1 = A + (size_t)(m0 + r1c) * K + kq1;
    const float* Wp0 = W + (size_t)(n0 + r0c) * K + kq0;
    const float* Wp1 = W + (size_t)(n0 + r1c) * K + kq1;

    float4 a0 = *reinterpret_cast<const float4*>(Ap0);
    float4 a1 = *reinterpret_cast<const float4*>(Ap1);
    float4 w0 = *reinterpret_cast<const float4*>(Wp0);
    float4 w1 = *reinterpret_cast<const float4*>(Wp1);

    for (int k0 = 0; k0 < K; k0 += 16) {
        __syncthreads();
        *reinterpret_cast<uint4*>(&As[r0c][kq0]) =
            make_uint4(f2tf32(a0.x), f2tf32(a0.y), f2tf32(a0.z), f2tf32(a0.w));
        *reinterpret_cast<uint4*>(&As[r1c][kq1]) =
            make_uint4(f2tf32(a1.x), f2tf32(a1.y), f2tf32(a1.z), f2tf32(a1.w));
        *reinterpret_cast<uint4*>(&Ws[r0c][kq0]) =
            make_uint4(f2tf32(w0.x), f2tf32(w0.y), f2tf32(w0.z), f2tf32(w0.w));
        *reinterpret_cast<uint4*>(&Ws[r1c][kq1]) =
            make_uint4(f2tf32(w1.x), f2tf32(w1.y), f2tf32(w1.z), f2tf32(w1.w));
        __syncthreads();

        if (k0 + 16 < K) {   // prefetch next K-block while mmas run
            a0 = *reinterpret_cast<const float4*>(Ap0 + k0 + 16);
            a1 = *reinterpret_cast<const float4*>(Ap1 + k0 + 16);
            w0 = *reinterpret_cast<const float4*>(Wp0 + k0 + 16);
            w1 = *reinterpret_cast<const float4*>(Wp1 + k0 + 16);
        }

        #pragma unroll
        for (int kk = 0; kk < 16; kk += 8) {
            int kb = kk + (lane & 3);
            uint32_t a[2][4];
            #pragma unroll
            for (int mi = 0; mi < 2; mi++) {
                int r = m0w + mi * 16 + (lane >> 2);
                a[mi][0] = As[r][kb];
                a[mi][1] = As[r + 8][kb];
                a[mi][2] = As[r][kb + 4];
                a[mi][3] = As[r + 8][kb + 4];
            }
            #pragma unroll
            for (int ni = 0; ni < 8; ni++) {
                int rn = n0w + ni * 8 + (lane >> 2);
                uint32_t b0 = Ws[rn][kb];
                uint32_t b1 = Ws[rn][kb + 4];
                mma_tf32(c[0][ni], a[0], b0, b1);
                mma_tf32(c[1][ni], a[1], b0, b1);
            }
        }
    }

    #pragma unroll
    for (int mi = 0; mi < 2; mi++) {
        int rbase = m0 + m0w + mi * 16 + (lane >> 2);
        #pragma unroll
        for (int ni = 0; ni < 8; ni++) {
            int col = n0 + n0w + ni * 8 + 2 * (lane & 3);
            float bv0 = bias[col], bv1 = bias[col + 1];
            #pragma unroll
            for (int half = 0; half < 2; half++) {
                int m = rbase + half * 8;
                float v0 = c[mi][ni][half * 2 + 0] + bv0;
                float v1 = c[mi][ni][half * 2 + 1] + bv1;
                if (BHTD) {
                    int b = m >> 11, t = m & 2047;
                    int h = col >> 6, d = col & 63;
                    size_t base = (((size_t)(b * NHEAD + h)) * SEQ + t) * HDIM + d;
                    C[base]     = v0;
                    C[base + 1] = v1;
                } else {
                    C[(size_t)m * EMBED + col]     = v0;
                    C[(size_t)m * EMBED + col + 1] = v1;
                }
            }
        }
    }
}

// Fused QKV projections: blockIdx.z selects which projection.
__global__ __launch_bounds__(256) void gemm_qkv(
    const float* __restrict__ q, const float* __restrict__ k, const float* __restrict__ v,
    const float* __restrict__ Wq, const float* __restrict__ bq,
    const float* __restrict__ Wk, const float* __restrict__ bk,
    const float* __restrict__ Wv, const float* __restrict__ bv,
    float* __restrict__ oq, float* __restrict__ ok, float* __restrict__ ov)
{
    int z = blockIdx.z;
    const float* A = (z == 0) ? q  : (z == 1) ? k  : v;
    const float* W = (z == 0) ? Wq : (z == 1) ? Wk : Wv;
    const float* B = (z == 0) ? bq : (z == 1) ? bk : bv;
    float*       C = (z == 0) ? oq : (z == 1) ? ok : ov;
    gemm_body<true>(A, W, B, C, blockIdx.y * 128, blockIdx.x * 128);
}

__global__ __launch_bounds__(256) void gemm_out(
    const float* __restrict__ A, const float* __restrict__ W,
    const float* __restrict__ bias, float* __restrict__ C)
{
    gemm_body<false>(A, W, bias, C, blockIdx.y * 128, blockIdx.x * 128);
}

// ---------------------------------------------------------------------------
// Flash attention via bf16 split mma (hi+lo), register-prefetch pipelined.
// ---------------------------------------------------------------------------
__device__ __forceinline__ void mma_bf16(float* c, const uint32_t* a,
                                         uint32_t b0, uint32_t b1) {
    asm volatile(
        "mma.sync.aligned.m16n8k16.row.col.f32.bf16.bf16.f32 "
        "{%0,%1,%2,%3}, {%4,%5,%6,%7}, {%8,%9}, {%0,%1,%2,%3};"
        : "+f"(c[0]), "+f"(c[1]), "+f"(c[2]), "+f"(c[3])
        : "r"(a[0]), "r"(a[1]), "r"(a[2]), "r"(a[3]), "r"(b0), "r"(b1));
}

__device__ __forceinline__ void pack2(float x, float y, uint32_t& hi, uint32_t& lo) {
    __nv_bfloat16 hx = __float2bfloat16(x), hy = __float2bfloat16(y);
    __nv_bfloat162 h2; h2.x = hx; h2.y = hy;
    hi = *reinterpret_cast<uint32_t*>(&h2);
    __nv_bfloat162 l2;
    l2.x = __float2bfloat16(x - __bfloat162float(hx));
    l2.y = __float2bfloat16(y - __bfloat162float(hy));
    lo = *reinterpret_cast<uint32_t*>(&l2);
}

#define FPITCH 72

__global__ __launch_bounds__(256, 1) void flash_attn_mma(const unsigned char* __restrict__ mask)
{
    extern __shared__ __align__(16) char smraw[];
    __nv_bfloat16* sQh = (__nv_bfloat16*)smraw;
    __nv_bfloat16* sQl = sQh + 128*FPITCH;
    __nv_bfloat16* sKh = sQl + 128*FPITCH;
    __nv_bfloat16* sKl = sKh + 64*FPITCH;
    __nv_bfloat16* sVh = sKl + 64*FPITCH;     // transposed: [d][s]
    __nv_bfloat16* sVl = sVh + 64*FPITCH;
    float* mfs = (float*)(sVl + 64*FPITCH);   // 64 floats

    int tid  = threadIdx.x;
    int lane = tid & 31, warp = tid >> 5;
    int grp  = lane >> 2, thr4 = lane & 3;
    int qt = (int)gridDim.x - 1 - (int)blockIdx.x;   // heavy tiles first
    int h = blockIdx.y, b = blockIdx.z;
    int qbase = qt * 128;

    const float* Qg = g_q + (((size_t)(b*NHEAD + h))*SEQ + qbase)*HDIM;
    const float* Kg = g_k + ((size_t)(b*NHEAD + h))*SEQ*HDIM;
    const float* Vg = g_v + ((size_t)(b*NHEAD + h))*SEQ*HDIM;
    const unsigned char* km = mask + (size_t)b*SEQ;

    // ---- stage Q (128x64) as bf16 hi/lo ----
    #pragma unroll
    for (int i = 0; i < 8; i++) {
        int e = tid + i*256;
        int r = e >> 4, c4 = (e & 15) << 2;
        float4 q = *reinterpret_cast<const float4*>(Qg + r*HDIM + c4);
        __nv_bfloat16* hp = sQh + r*FPITCH + c4;
        __nv_bfloat16* lp = sQl + r*FPITCH + c4;
        __nv_bfloat16 h0 = __float2bfloat16(q.x), h1 = __float2bfloat16(q.y),
                      h2 = __float2bfloat16(q.z), h3 = __float2bfloat16(q.w);
        hp[0]=h0; hp[1]=h1; hp[2]=h2; hp[3]=h3;
        lp[0]=__float2bfloat16(q.x-__bfloat162float(h0));
        lp[1]=__float2bfloat16(q.y-__bfloat162float(h1));
        lp[2]=__float2bfloat16(q.z-__bfloat162float(h2));
        lp[3]=__float2bfloat16(q.w-__bfloat162float(h3));
    }

    // per-thread K/V tile load coords
    int lr = tid >> 4;               // 0..15 base row
    int lc4 = (tid & 15) << 2;       // 0..60
    const float* Kp = Kg + (size_t)lr*HDIM + lc4;
    const float* Vp = Vg + (size_t)lr*HDIM + lc4;

    // prefetch tile 0
    float4 kreg[4], vreg[4];
    #pragma unroll
    for (int i = 0; i < 4; i++) {
        kreg[i] = *reinterpret_cast<const float4*>(Kp + (size_t)(i*16)*HDIM);
        vreg[i] = *reinterpret_cast<const float4*>(Vp + (size_t)(i*16)*HDIM);
    }
    unsigned char mreg = (tid < 64) ? km[tid] : 0;

    __syncthreads();

    // ---- preload Q fragments ----
    uint32_t qh[4][4], ql[4][4];
    {
        int rl = warp*16 + grp;
        #pragma unroll
        for (int ks = 0; ks < 4; ks++) {
            int cc = thr4*2 + ks*16;
            qh[ks][0] = *(const uint32_t*)(sQh + rl*FPITCH + cc);
            qh[ks][1] = *(const uint32_t*)(sQh + (rl+8)*FPITCH + cc);
            qh[ks][2] = *(const uint32_t*)(sQh + rl*FPITCH + cc + 8);
            qh[ks][3] = *(const uint32_t*)(sQh + (rl+8)*FPITCH + cc + 8);
            ql[ks][0] = *(const uint32_t*)(sQl + rl*FPITCH + cc);
            ql[ks][1] = *(const uint32_t*)(sQl + (rl+8)*FPITCH + cc);
            ql[ks][2] = *(const uint32_t*)(sQl + rl*FPITCH + cc + 8);
            ql[ks][3] = *(const uint32_t*)(sQl + (rl+8)*FPITCH + cc + 8);
        }
    }

    int row0 = qbase + warp*16 + grp;
    int row1 = row0 + 8;

    float m0 = -1e30f, m1 = -1e30f, l0 = 0.f, l1 = 0.f;
    float o[8][4];
    #pragma unroll
    for (int j = 0; j < 8; j++)
        #pragma unroll
        for (int q = 0; q < 4; q++) o[j][q] = 0.f;

    const int ntiles = 2*qt + 2;
    for (int jt = 0; jt < ntiles; jt++) {
        int s0 = jt * 64;
        __syncthreads();
        // store prefetched K/V tile (convert + split; V transposed)
        #pragma unroll
        for (int i = 0; i < 4; i++) {
            int r = lr + i*16;
            __nv_bfloat16* hp = sKh + r*FPITCH + lc4;
            __nv_bfloat16* lp = sKl + r*FPITCH + lc4;
            float4 kk = kreg[i];
            __nv_bfloat16 h0 = __float2bfloat16(kk.x), h1 = __float2bfloat16(kk.y),
                          h2 = __float2bfloat16(kk.z), h3 = __float2bfloat16(kk.w);
            hp[0]=h0; hp[1]=h1; hp[2]=h2; hp[3]=h3;
            lp[0]=__float2bfloat16(kk.x-__bfloat162float(h0));
            lp[1]=__float2bfloat16(kk.y-__bfloat162float(h1));
            lp[2]=__float2bfloat16(kk.z-__bfloat162float(h2));
            lp[3]=__float2bfloat16(kk.w-__bfloat162float(h3));

            float4 vv = vreg[i];
            float vf[4] = {vv.x, vv.y, vv.z, vv.w};
            #pragma unroll
            for (int u = 0; u < 4; u++) {
                __nv_bfloat16 vh = __float2bfloat16(vf[u]);
                sVh[(lc4+u)*FPITCH + r] = vh;
                sVl[(lc4+u)*FPITCH + r] = __float2bfloat16(vf[u]-__bfloat162float(vh));
            }
        }
        if (tid < 64) mfs[tid] = mreg ? -1e30f : 0.0f;
        __syncthreads();

        // prefetch next tile while mmas run
        if (jt + 1 < ntiles) {
            size_t off = (size_t)(s0 + 64) * HDIM;
            #pragma unroll
            for (int i = 0; i < 4; i++) {
                kreg[i] = *reinterpret_cast<const float4*>(Kp + off + (size_t)(i*16)*HDIM);
                vreg[i] = *reinterpret_cast<const float4*>(Vp + off + (size_t)(i*16)*HDIM);
            }
            if (tid < 64) mreg = km[s0 + 64 + tid];
        }

        // ---- S = Q K^T ----
        float s[8][4];
        #pragma unroll
        for (int j = 0; j < 8; j++)
            #pragma unroll
            for (int q = 0; q < 4; q++) s[j][q] = 0.f;

        #pragma unroll
        for (int ks = 0; ks < 4; ks++) {
            int cc = thr4*2 + ks*16;
            #pragma unroll
            for (int j = 0; j < 8; j++) {
                int n = j*8 + grp;
                uint32_t bh0 = *(const uint32_t*)(sKh + n*FPITCH + cc);
                uint32_t bh1 = *(const uint32_t*)(sKh + n*FPITCH + cc + 8);
                uint32_t bl0 = *(const uint32_t*)(sKl + n*FPITCH + cc);
                uint32_t bl1 = *(const uint32_t*)(sKl + n*FPITCH + cc + 8);
                mma_bf16(s[j], qh[ks], bh0, bh1);
                mma_bf16(s[j], qh[ks], bl0, bl1);
                mma_bf16(s[j], ql[ks], bh0, bh1);
            }
        }

        // ---- scale + masks + online softmax ----
        bool diag = (jt >= 2*qt);
        float nm0 = m0, nm1 = m1;
        #pragma unroll
        for (int j = 0; j < 8; j++) {
            int cb = 8*j + 2*thr4;
            float f0 = mfs[cb], f1 = mfs[cb+1];
            float v00 = fmaf(s[j][0], 0.125f, f0);
            float v01 = fmaf(s[j][1], 0.125f, f1);
            float v10 = fmaf(s[j][2], 0.125f, f0);
            float v11 = fmaf(s[j][3], 0.125f, f1);
            if (diag) {
                int ca = s0 + cb;
                if (ca     > row0) v00 = -1e30f;
                if (ca + 1 > row0) v01 = -1e30f;
                if (ca     > row1) v10 = -1e30f;
                if (ca + 1 > row1) v11 = -1e30f;
            }
            s[j][0] = v00; s[j][1] = v01; s[j][2] = v10; s[j][3] = v11;
            nm0 = fmaxf(nm0, fmaxf(v00, v01));
            nm1 = fmaxf(nm1, fmaxf(v10, v11));
        }
        nm0 = fmaxf(nm0, __shfl_xor_sync(0xffffffffu, nm0, 1));
        nm0 = fmaxf(nm0, __shfl_xor_sync(0xffffffffu, nm0, 2));
        nm1 = fmaxf(nm1, __shfl_xor_sync(0xffffffffu, nm1, 1));
        nm1 = fmaxf(nm1, __shfl_xor_sync(0xffffffffu, nm1, 2));

        float c0 = __expf(m0 - nm0), c1 = __expf(m1 - nm1);
        m0 = nm0; m1 = nm1;

        float ls0 = 0.f, ls1 = 0.f;
        #pragma unroll
        for (int j = 0; j < 8; j++) {
            s[j][0] = __expf(s[j][0] - m0);
            s[j][1] = __expf(s[j][1] - m0);
            s[j][2] = __expf(s[j][2] - m1);
            s[j][3] = __expf(s[j][3] - m1);
            ls0 += s[j][0] + s[j][1];
            ls1 += s[j][2] + s[j][3];
        }
        ls0 += __shfl_xor_sync(0xffffffffu, ls0, 1);
        ls0 += __shfl_xor_sync(0xffffffffu, ls0, 2);
        ls1 += __shfl_xor_sync(0xffffffffu, ls1, 1);
        ls1 += __shfl_xor_sync(0xffffffffu, ls1, 2);
        l0 = l0*c0 + ls0;
        l1 = l1*c1 + ls1;

        #pragma unroll
        for (int j = 0; j < 8; j++) {
            o[j][0] *= c0; o[j][1] *= c0;
            o[j][2] *= c1; o[j][3] *= c1;
        }

        // ---- O += P V ----
        #pragma unroll
        for (int ks = 0; ks < 4; ks++) {
            uint32_t ph[4], pl[4];
            float* sa = s[2*ks];
            float* sb = s[2*ks + 1];
            pack2(sa[0], sa[1], ph[0], pl[0]);
            pack2(sa[2], sa[3], ph[1], pl[1]);
            pack2(sb[0], sb[1], ph[2], pl[2]);
            pack2(sb[2], sb[3], ph[3], pl[3]);
            int cc = thr4*2 + ks*16;
            #pragma unroll
            for (int j = 0; j < 8; j++) {
                int n = j*8 + grp;
                uint32_t vh0 = *(const uint32_t*)(sVh + n*FPITCH + cc);
                uint32_t vh1 = *(const uint32_t*)(sVh + n*FPITCH + cc + 8);
                uint32_t vl0 = *(const uint32_t*)(sVl + n*FPITCH + cc);
                uint32_t vl1 = *(const uint32_t*)(sVl + n*FPITCH + cc + 8);
                mma_bf16(o[j], ph, vh0, vh1);
                mma_bf16(o[j], ph, vl0, vl1);
                mma_bf16(o[j], pl, vh0, vh1);
            }
        }
    }

    // ---- epilogue ----
    float inv0 = 1.f / l0, inv1 = 1.f / l1;
    float* O0 = g_ao + ((size_t)(b*SEQ) + row0)*EMBED + h*HDIM;
    float* O1 = g_ao + ((size_t)(b*SEQ) + row1)*EMBED + h*HDIM;
    #pragma unroll
    for (int j = 0; j < 8; j++) {
        int col = 8*j + 2*thr4;
        *reinterpret_cast<float2*>(O0 + col) = make_float2(o[j][0]*inv0, o[j][1]*inv0);
        *reinterpret_cast<float2*>(O1 + col) = make_float2(o[j][2]*inv1, o[j][3]*inv1);
    }
}

// ---------------------------------------------------------------------------
extern "C" void kernel_launch(void* const* d_in, const int* in_sizes, int n_in,
                              void* d_out, int out_size)
{
    const float* query = (const float*)d_in[0];
    const float* key   = (const float*)d_in[1];
    const float* value = (const float*)d_in[2];
    const unsigned char* kpm = (const unsigned char*)d_in[3];
    const float* Wq = (const float*)d_in[4];
    const float* bq = (const float*)d_in[5];
    const float* Wk = (const float*)d_in[6];
    const float* bk = (const float*)d_in[7];
    const float* Wv = (const float*)d_in[8];
    const float* bv = (const float*)d_in[9];
    const float* Wo = (const float*)d_in[10];
    const float* bo = (const float*)d_in[11];
    float* out = (float*)d_out;

    float *qp, *kp, *vp, *aop;
    cudaGetSymbolAddress((void**)&qp,  g_q);
    cudaGetSymbolAddress((void**)&kp,  g_k);
    cudaGetSymbolAddress((void**)&vp,  g_v);
    cudaGetSymbolAddress((void**)&aop, g_ao);

    dim3 gqkv(EMBED/128, MROWS/128, 3);   // (8, 32, 3) = 768 CTAs
    gemm_qkv<<<gqkv, 256>>>(query, key, value, Wq, bq, Wk, bk, Wv, bv, qp, kp, vp);

    const int FLASH_SMEM = (128*2 + 64*4) * FPITCH * 2 + 64 * 4;  // 73984
    cudaFuncSetAttribute(flash_attn_mma, cudaFuncAttributeMaxDynamicSharedMemorySize, FLASH_SMEM);
    flash_attn_mma<<<dim3(SEQ/128, NHEAD, BATCH), 256, FLASH_SMEM>>>(kpm);

    dim3 gout(EMBED/128, MROWS/128);
    gemm_out<<<gout, 256>>>(aop, Wo, bo, out);
}

// round 9
// speedup vs baseline: 2.6481x; 1.0077x over previous
#include <cuda_runtime.h>
#include <cuda_bf16.h>
#include <cstdint>

#define EMBED 1024
#define NHEAD 16
#define HDIM  64
#define BATCH 2
#define SEQ   2048
#define MROWS (BATCH*SEQ)   // 4096

__device__ float g_q[BATCH*NHEAD*SEQ*HDIM];   // [B,H,T,D]
__device__ float g_k[BATCH*NHEAD*SEQ*HDIM];
__device__ float g_v[BATCH*NHEAD*SEQ*HDIM];
__device__ float g_ao[MROWS*EMBED];           // attention out, [B,T,E]

// ---------------------------------------------------------------------------
// TF32 tensor-core GEMM: C = A @ W^T + bias.
// BK=32, double-buffered smem (one __syncthreads per iter, STS overlapped
// with mma), register prefetch of next chunk. Pitch 36 words: frag loads
// (4r + kb) mod 32 all-distinct -> conflict-free.
// ---------------------------------------------------------------------------
__device__ __forceinline__ uint32_t f2tf32(float x) {
    uint32_t r;
    asm("cvt.rna.tf32.f32 %0, %1;" : "=r"(r) : "f"(x));
    return r;
}

__device__ __forceinline__ void mma_tf32(float* c, const uint32_t* a,
                                         uint32_t b0, uint32_t b1) {
    asm volatile(
        "mma.sync.aligned.m16n8k8.row.col.f32.tf32.tf32.f32 "
        "{%0,%1,%2,%3}, {%4,%5,%6,%7}, {%8,%9}, {%0,%1,%2,%3};"
        : "+f"(c[0]), "+f"(c[1]), "+f"(c[2]), "+f"(c[3])
        : "r"(a[0]), "r"(a[1]), "r"(a[2]), "r"(a[3]), "r"(b0), "r"(b1));
}

#define GP 36                    // words per row (32 + 4 pad)
#define GA_WORDS (128*GP)        // one 128x32 fp32(tf32) tile = 4608 words
#define GSTAGE   (2*GA_WORDS)    // A + W per stage
#define GEMM_SMEM (2*GSTAGE*4)   // 73728 bytes

template<bool BHTD>
__device__ __forceinline__ void gemm_body(
    const float* __restrict__ A, const float* __restrict__ W,
    const float* __restrict__ bias, float* __restrict__ C,
    int m0, int n0)
{
    const int K = EMBED;
    extern __shared__ uint32_t gsm[];   // [2 stages][A | W]

    int tid  = threadIdx.x;
    int lane = tid & 31;
    int warp = tid >> 5;
    int wm = warp >> 1, wn = warp & 1;
    int m0w = wm * 32, n0w = wn * 64;

    float c[2][8][4];
    #pragma unroll
    for (int mi = 0; mi < 2; mi++)
        #pragma unroll
        for (int ni = 0; ni < 8; ni++)
            #pragma unroll
            for (int q = 0; q < 4; q++) c[mi][ni][q] = 0.f;

    // per-thread load slots: i=0..3, idx = tid + i*256, r = idx>>3, c4 = (idx&7)*4
    float4 ar[4], wr[4];
    #pragma unroll
    for (int i = 0; i < 4; i++) {
        int idx = tid + i*256;
        int r = idx >> 3, c4 = (idx & 7) << 2;
        ar[i] = *reinterpret_cast<const float4*>(A + (size_t)(m0 + r) * K + c4);
        wr[i] = *reinterpret_cast<const float4*>(W + (size_t)(n0 + r) * K + c4);
    }

    // STS of current regs into stage s
    auto sts_stage = [&](int s) {
        #pragma unroll
        for (int i = 0; i < 4; i++) {
            int idx = tid + i*256;
            int r = idx >> 3, c4 = (idx & 7) << 2;
            *reinterpret_cast<uint4*>(&gsm[s*GSTAGE + r*GP + c4]) =
                make_uint4(f2tf32(ar[i].x), f2tf32(ar[i].y), f2tf32(ar[i].z), f2tf32(ar[i].w));
            *reinterpret_cast<uint4*>(&gsm[s*GSTAGE + GA_WORDS + r*GP + c4]) =
                make_uint4(f2tf32(wr[i].x), f2tf32(wr[i].y), f2tf32(wr[i].z), f2tf32(wr[i].w));
        }
    };

    sts_stage(0);

    const int NCHUNK = K / 32;   // 32
    for (int ch = 0; ch < NCHUNK; ch++) {
        __syncthreads();
        int s = ch & 1;

        if (ch + 1 < NCHUNK) {   // prefetch next chunk while mmas run
            int k0 = (ch + 1) * 32;
            #pragma unroll
            for (int i = 0; i < 4; i++) {
                int idx = tid + i*256;
                int r = idx >> 3, c4 = (idx & 7) << 2;
                ar[i] = *reinterpret_cast<const float4*>(A + (size_t)(m0 + r) * K + k0 + c4);
                wr[i] = *reinterpret_cast<const float4*>(W + (size_t)(n0 + r) * K + k0 + c4);
            }
        }

        const uint32_t* As = gsm + s*GSTAGE;
        const uint32_t* Ws = As + GA_WORDS;
        #pragma unroll
        for (int kk = 0; kk < 32; kk += 8) {
            int kb = kk + (lane & 3);
            uint32_t a[2][4];
            #pragma unroll
            for (int mi = 0; mi < 2; mi++) {
                int r = m0w + mi * 16 + (lane >> 2);
                a[mi][0] = As[r*GP + kb];
                a[mi][1] = As[(r + 8)*GP + kb];
                a[mi][2] = As[r*GP + kb + 4];
                a[mi][3] = As[(r + 8)*GP + kb + 4];
            }
            #pragma unroll
            for (int ni = 0; ni < 8; ni++) {
                int rn = n0w + ni * 8 + (lane >> 2);
                uint32_t b0 = Ws[rn*GP + kb];
                uint32_t b1 = Ws[rn*GP + kb + 4];
                mma_tf32(c[0][ni], a[0], b0, b1);
                mma_tf32(c[1][ni], a[1], b0, b1);
            }
        }

        if (ch + 1 < NCHUNK) sts_stage((ch + 1) & 1);   // write other stage (overlaps mma drain)
    }

    #pragma unroll
    for (int mi = 0; mi < 2; mi++) {
        int rbase = m0 + m0w + mi * 16 + (lane >> 2);
        #pragma unroll
        for (int ni = 0; ni < 8; ni++) {
            int col = n0 + n0w + ni * 8 + 2 * (lane & 3);
            float bv0 = bias[col], bv1 = bias[col + 1];
            #pragma unroll
            for (int half = 0; half < 2; half++) {
                int m = rbase + half * 8;
                float v0 = c[mi][ni][half * 2 + 0] + bv0;
                float v1 = c[mi][ni][half * 2 + 1] + bv1;
                if (BHTD) {
                    int b = m >> 11, t = m & 2047;
                    int h = col >> 6, d = col & 63;
                    size_t base = (((size_t)(b * NHEAD + h)) * SEQ + t) * HDIM + d;
                    C[base]     = v0;
                    C[base + 1] = v1;
                } else {
                    C[(size_t)m * EMBED + col]     = v0;
                    C[(size_t)m * EMBED + col + 1] = v1;
                }
            }
        }
    }
}

__global__ __launch_bounds__(256) void gemm_qkv(
    const float* __restrict__ q, const float* __restrict__ k, const float* __restrict__ v,
    const float* __restrict__ Wq, const float* __restrict__ bq,
    const float* __restrict__ Wk, const float* __restrict__ bk,
    const float* __restrict__ Wv, const float* __restrict__ bv,
    float* __restrict__ oq, float* __restrict__ ok, float* __restrict__ ov)
{
    int z = blockIdx.z;
    const float* A = (z == 0) ? q  : (z == 1) ? k  : v;
    const float* W = (z == 0) ? Wq : (z == 1) ? Wk : Wv;
    const float* B = (z == 0) ? bq : (z == 1) ? bk : bv;
    float*       C = (z == 0) ? oq : (z == 1) ? ok : ov;
    gemm_body<true>(A, W, B, C, blockIdx.y * 128, blockIdx.x * 128);
}

__global__ __launch_bounds__(256) void gemm_out(
    const float* __restrict__ A, const float* __restrict__ W,
    const float* __restrict__ bias, float* __restrict__ C)
{
    gemm_body<false>(A, W, bias, C, blockIdx.y * 128, blockIdx.x * 128);
}

// ---------------------------------------------------------------------------
// Flash attention via bf16 split mma (hi+lo, 3 terms).
// v2: Q smem region reused for K/V after Q frags are in regs (37 KB smem),
// __launch_bounds__(256,2) for 2 CTAs/SM; latency hidden by occupancy.
// ---------------------------------------------------------------------------
__device__ __forceinline__ void mma_bf16(float* c, const uint32_t* a,
                                         uint32_t b0, uint32_t b1) {
    asm volatile(
        "mma.sync.aligned.m16n8k16.row.col.f32.bf16.bf16.f32 "
        "{%0,%1,%2,%3}, {%4,%5,%6,%7}, {%8,%9}, {%0,%1,%2,%3};"
        : "+f"(c[0]), "+f"(c[1]), "+f"(c[2]), "+f"(c[3])
        : "r"(a[0]), "r"(a[1]), "r"(a[2]), "r"(a[3]), "r"(b0), "r"(b1));
}

__device__ __forceinline__ void pack2(float x, float y, uint32_t& hi, uint32_t& lo) {
    __nv_bfloat16 hx = __float2bfloat16(x), hy = __float2bfloat16(y);
    __nv_bfloat162 h2; h2.x = hx; h2.y = hy;
    hi = *reinterpret_cast<uint32_t*>(&h2);
    __nv_bfloat162 l2;
    l2.x = __float2bfloat16(x - __bfloat162float(hx));
    l2.y = __float2bfloat16(y - __bfloat162float(hy));
    lo = *reinterpret_cast<uint32_t*>(&l2);
}

#define FPITCH 72
// K/V region (reusing Q space): sKh 64*72*2=9216 B, sKl, sVh, sVl; mfs after.
#define FLASH_SMEM (4*64*FPITCH*2 + 64*4)   // 37120

__global__ __launch_bounds__(256, 2) void flash_attn_mma(const unsigned char* __restrict__ mask)
{
    extern __shared__ __align__(16) char smraw[];
    // Phase 1: Q staging occupies [0, 36864)
    __nv_bfloat16* sQh = (__nv_bfloat16*)smraw;
    __nv_bfloat16* sQl = sQh + 128*FPITCH;
    // Phase 2 (after Q frags in regs): same bytes become K/V
    __nv_bfloat16* sKh = (__nv_bfloat16*)smraw;
    __nv_bfloat16* sKl = sKh + 64*FPITCH;
    __nv_bfloat16* sVh = sKl + 64*FPITCH;     // transposed: [d][s]
    __nv_bfloat16* sVl = sVh + 64*FPITCH;
    float* mfs = (float*)(smraw + 4*64*FPITCH*2);   // 64 floats

    int tid  = threadIdx.x;
    int lane = tid & 31, warp = tid >> 5;
    int grp  = lane >> 2, thr4 = lane & 3;
    int qt = (int)gridDim.x - 1 - (int)blockIdx.x;   // heavy tiles first
    int h = blockIdx.y, b = blockIdx.z;
    int qbase = qt * 128;

    const float* Qg = g_q + (((size_t)(b*NHEAD + h))*SEQ + qbase)*HDIM;
    const float* Kg = g_k + ((size_t)(b*NHEAD + h))*SEQ*HDIM;
    const float* Vg = g_v + ((size_t)(b*NHEAD + h))*SEQ*HDIM;
    const unsigned char* km = mask + (size_t)b*SEQ;

    // ---- stage Q (128x64) as bf16 hi/lo ----
    #pragma unroll
    for (int i = 0; i < 8; i++) {
        int e = tid + i*256;
        int r = e >> 4, c4 = (e & 15) << 2;
        float4 q = *reinterpret_cast<const float4*>(Qg + r*HDIM + c4);
        __nv_bfloat16* hp = sQh + r*FPITCH + c4;
        __nv_bfloat16* lp = sQl + r*FPITCH + c4;
        __nv_bfloat16 h0 = __float2bfloat16(q.x), h1 = __float2bfloat16(q.y),
                      h2 = __float2bfloat16(q.z), h3 = __float2bfloat16(q.w);
        hp[0]=h0; hp[1]=h1; hp[2]=h2; hp[3]=h3;
        lp[0]=__float2bfloat16(q.x-__bfloat162float(h0));
        lp[1]=__float2bfloat16(q.y-__bfloat162float(h1));
        lp[2]=__float2bfloat16(q.z-__bfloat162float(h2));
        lp[3]=__float2bfloat16(q.w-__bfloat162float(h3));
    }
    __syncthreads();

    // ---- preload Q fragments (then smem is free for K/V) ----
    uint32_t qh[4][4], ql[4][4];
    {
        int rl = warp*16 + grp;
        #pragma unroll
        for (int ks = 0; ks < 4; ks++) {
            int cc = thr4*2 + ks*16;
            qh[ks][0] = *(const uint32_t*)(sQh + rl*FPITCH + cc);
            qh[ks][1] = *(const uint32_t*)(sQh + (rl+8)*FPITCH + cc);
            qh[ks][2] = *(const uint32_t*)(sQh + rl*FPITCH + cc + 8);
            qh[ks][3] = *(const uint32_t*)(sQh + (rl+8)*FPITCH + cc + 8);
            ql[ks][0] = *(const uint32_t*)(sQl + rl*FPITCH + cc);
            ql[ks][1] = *(const uint32_t*)(sQl + (rl+8)*FPITCH + cc);
            ql[ks][2] = *(const uint32_t*)(sQl + rl*FPITCH + cc + 8);
            ql[ks][3] = *(const uint32_t*)(sQl + (rl+8)*FPITCH + cc + 8);
        }
    }

    int row0 = qbase + warp*16 + grp;
    int row1 = row0 + 8;

    float m0 = -1e30f, m1 = -1e30f, l0 = 0.f, l1 = 0.f;
    float o[8][4];
    #pragma unroll
    for (int j = 0; j < 8; j++)
        #pragma unroll
        for (int q = 0; q < 4; q++) o[j][q] = 0.f;

    int lr = tid >> 4;               // 0..15 base row of K/V tile load
    int lc4 = (tid & 15) << 2;       // 0..60
    const float* Kp = Kg + (size_t)lr*HDIM + lc4;
    const float* Vp = Vg + (size_t)lr*HDIM + lc4;

    const int ntiles = 2*qt + 2;
    for (int jt = 0; jt < ntiles; jt++) {
        int s0 = jt * 64;
        __syncthreads();   // everyone done reading previous K/V (and Q frags on jt=0)
        size_t off = (size_t)s0 * HDIM;
        #pragma unroll
        for (int i = 0; i < 4; i++) {
            int r = lr + i*16;
            float4 kk = *reinterpret_cast<const float4*>(Kp + off + (size_t)(i*16)*HDIM);
            __nv_bfloat16* hp = sKh + r*FPITCH + lc4;
            __nv_bfloat16* lp = sKl + r*FPITCH + lc4;
            __nv_bfloat16 h0 = __float2bfloat16(kk.x), h1 = __float2bfloat16(kk.y),
                          h2 = __float2bfloat16(kk.z), h3 = __float2bfloat16(kk.w);
            hp[0]=h0; hp[1]=h1; hp[2]=h2; hp[3]=h3;
            lp[0]=__float2bfloat16(kk.x-__bfloat162float(h0));
            lp[1]=__float2bfloat16(kk.y-__bfloat162float(h1));
            lp[2]=__float2bfloat16(kk.z-__bfloat162float(h2));
            lp[3]=__float2bfloat16(kk.w-__bfloat162float(h3));

            float4 vv = *reinterpret_cast<const float4*>(Vp + off + (size_t)(i*16)*HDIM);
            float vf[4] = {vv.x, vv.y, vv.z, vv.w};
            #pragma unroll
            for (int u = 0; u < 4; u++) {
                __nv_bfloat16 vh = __float2bfloat16(vf[u]);
                sVh[(lc4+u)*FPITCH + r] = vh;
                sVl[(lc4+u)*FPITCH + r] = __float2bfloat16(vf[u]-__bfloat162float(vh));
            }
        }
        if (tid < 64) mfs[tid] = km[s0 + tid] ? -1e30f : 0.0f;
        __syncthreads();

        // ---- S = Q K^T ----
        float s[8][4];
        #pragma unroll
        for (int j = 0; j < 8; j++)
            #pragma unroll
            for (int q = 0; q < 4; q++) s[j][q] = 0.f;

        #pragma unroll
        for (int ks = 0; ks < 4; ks++) {
            int cc = thr4*2 + ks*16;
            #pragma unroll
            for (int j = 0; j < 8; j++) {
                int n = j*8 + grp;
                uint32_t bh0 = *(const uint32_t*)(sKh + n*FPITCH + cc);
                uint32_t bh1 = *(const uint32_t*)(sKh + n*FPITCH + cc + 8);
                uint32_t bl0 = *(const uint32_t*)(sKl + n*FPITCH + cc);
                uint32_t bl1 = *(const uint32_t*)(sKl + n*FPITCH + cc + 8);
                mma_bf16(s[j], qh[ks], bh0, bh1);
                mma_bf16(s[j], qh[ks], bl0, bl1);
                mma_bf16(s[j], ql[ks], bh0, bh1);
            }
        }

        // ---- scale + masks + online softmax ----
        bool diag = (jt >= 2*qt);
        float nm0 = m0, nm1 = m1;
        #pragma unroll
        for (int j = 0; j < 8; j++) {
            int cb = 8*j + 2*thr4;
            float f0 = mfs[cb], f1 = mfs[cb+1];
            float v00 = fmaf(s[j][0], 0.125f, f0);
            float v01 = fmaf(s[j][1], 0.125f, f1);
            float v10 = fmaf(s[j][2], 0.125f, f0);
            float v11 = fmaf(s[j][3], 0.125f, f1);
            if (diag) {
                int ca = s0 + cb;
                if (ca     > row0) v00 = -1e30f;
                if (ca + 1 > row0) v01 = -1e30f;
                if (ca     > row1) v10 = -1e30f;
                if (ca + 1 > row1) v11 = -1e30f;
            }
            s[j][0] = v00; s[j][1] = v01; s[j][2] = v10; s[j][3] = v11;
            nm0 = fmaxf(nm0, fmaxf(v00, v01));
            nm1 = fmaxf(nm1, fmaxf(v10, v11));
        }
        nm0 = fmaxf(nm0, __shfl_xor_sync(0xffffffffu, nm0, 1));
        nm0 = fmaxf(nm0, __shfl_xor_sync(0xffffffffu, nm0, 2));
        nm1 = fmaxf(nm1, __shfl_xor_sync(0xffffffffu, nm1, 1));
        nm1 = fmaxf(nm1, __shfl_xor_sync(0xffffffffu, nm1, 2));

        float c0 = __expf(m0 - nm0), c1 = __expf(m1 - nm1);
        m0 = nm0; m1 = nm1;

        float ls0 = 0.f, ls1 = 0.f;
        #pragma unroll
        for (int j = 0; j < 8; j++) {
            s[j][0] = __expf(s[j][0] - m0);
            s[j][1] = __expf(s[j][1] - m0);
            s[j][2] = __expf(s[j][2] - m1);
            s[j][3] = __expf(s[j][3] - m1);
            ls0 += s[j][0] + s[j][1];
            ls1 += s[j][2] + s[j][3];
        }
        ls0 += __shfl_xor_sync(0xffffffffu, ls0, 1);
        ls0 += __shfl_xor_sync(0xffffffffu, ls0, 2);
        ls1 += __shfl_xor_sync(0xffffffffu, ls1, 1);
        ls1 += __shfl_xor_sync(0xffffffffu, ls1, 2);
        l0 = l0*c0 + ls0;
        l1 = l1*c1 + ls1;

        #pragma unroll
        for (int j = 0; j < 8; j++) {
            o[j][0] *= c0; o[j][1] *= c0;
            o[j][2] *= c1; o[j][3] *= c1;
        }

        // ---- O += P V ----
        #pragma unroll
        for (int ks = 0; ks < 4; ks++) {
            uint32_t ph[4], pl[4];
            float* sa = s[2*ks];
            float* sb = s[2*ks + 1];
            pack2(sa[0], sa[1], ph[0], pl[0]);
            pack2(sa[2], sa[3], ph[1], pl[1]);
            pack2(sb[0], sb[1], ph[2], pl[2]);
            pack2(sb[2], sb[3], ph[3], pl[3]);
            int cc = thr4*2 + ks*16;
            #pragma unroll
            for (int j = 0; j < 8; j++) {
                int n = j*8 + grp;
                uint32_t vh0 = *(const uint32_t*)(sVh + n*FPITCH + cc);
                uint32_t vh1 = *(const uint32_t*)(sVh + n*FPITCH + cc + 8);
                uint32_t vl0 = *(const uint32_t*)(sVl + n*FPITCH + cc);
                uint32_t vl1 = *(const uint32_t*)(sVl + n*FPITCH + cc + 8);
                mma_bf16(o[j], ph, vh0, vh1);
                mma_bf16(o[j], ph, vl0, vl1);
                mma_bf16(o[j], pl, vh0, vh1);
            }
        }
    }

    // ---- epilogue ----
    float inv0 = 1.f / l0, inv1 = 1.f / l1;
    float* O0 = g_ao + ((size_t)(b*SEQ) + row0)*EMBED + h*HDIM;
    float* O1 = g_ao + ((size_t)(b*SEQ) + row1)*EMBED + h*HDIM;
    #pragma unroll
    for (int j = 0; j < 8; j++) {
        int col = 8*j + 2*thr4;
        *reinterpret_cast<float2*>(O0 + col) = make_float2(o[j][0]*inv0, o[j][1]*inv0);
        *reinterpret_cast<float2*>(O1 + col) = make_float2(o[j][2]*inv1, o[j][3]*inv1);
    }
}

// ---------------------------------------------------------------------------
extern "C" void kernel_launch(void* const* d_in, const int* in_sizes, int n_in,
                              void* d_out, int out_size)
{
    const float* query = (const float*)d_in[0];
    const float* key   = (const float*)d_in[1];
    const float* value = (const float*)d_in[2];
    const unsigned char* kpm = (const unsigned char*)d_in[3];
    const float* Wq = (const float*)d_in[4];
    const float* bq = (const float*)d_in[5];
    const float* Wk = (const float*)d_in[6];
    const float* bk = (const float*)d_in[7];
    const float* Wv = (const float*)d_in[8];
    const float* bv = (const float*)d_in[9];
    const float* Wo = (const float*)d_in[10];
    const float* bo = (const float*)d_in[11];
    float* out = (float*)d_out;

    float *qp, *kp, *vp, *aop;
    cudaGetSymbolAddress((void**)&qp,  g_q);
    cudaGetSymbolAddress((void**)&kp,  g_k);
    cudaGetSymbolAddress((void**)&vp,  g_v);
    cudaGetSymbolAddress((void**)&aop, g_ao);

    cudaFuncSetAttribute(gemm_qkv, cudaFuncAttributeMaxDynamicSharedMemorySize, GEMM_SMEM);
    cudaFuncSetAttribute(gemm_out, cudaFuncAttributeMaxDynamicSharedMemorySize, GEMM_SMEM);

    dim3 gqkv(EMBED/128, MROWS/128, 3);   // (8, 32, 3) = 768 CTAs
    gemm_qkv<<<gqkv, 256, GEMM_SMEM>>>(query, key, value, Wq, bq, Wk, bk, Wv, bv, qp, kp, vp);

    cudaFuncSetAttribute(flash_attn_mma, cudaFuncAttributeMaxDynamicSharedMemorySize, FLASH_SMEM);
    flash_attn_mma<<<dim3(SEQ/128, NHEAD, BATCH), 256, FLASH_SMEM>>>(kpm);

    dim3 gout(EMBED/128, MROWS/128);
    gemm_out<<<gout, 256, GEMM_SMEM>>>(aop, Wo, bo, out);
}

// round 10
// speedup vs baseline: 2.9248x; 1.1045x over previous
#include <cuda_runtime.h>
#include <cuda_bf16.h>
#include <cstdint>

#define EMBED 1024
#define NHEAD 16
#define HDIM  64
#define BATCH 2
#define SEQ   2048
#define MROWS (BATCH*SEQ)   // 4096

// tf32-rounded copies of inputs / weights
__device__ float g_qc[MROWS*EMBED];
__device__ float g_kc[MROWS*EMBED];
__device__ float g_vc[MROWS*EMBED];
__device__ float g_w4[4*EMBED*EMBED];         // Wq | Wk | Wv | Wo
// bf16 hi/lo projections, [B,H,T,D]
__device__ __nv_bfloat16 g_qh[BATCH*NHEAD*SEQ*HDIM];
__device__ __nv_bfloat16 g_ql[BATCH*NHEAD*SEQ*HDIM];
__device__ __nv_bfloat16 g_kh[BATCH*NHEAD*SEQ*HDIM];
__device__ __nv_bfloat16 g_kl[BATCH*NHEAD*SEQ*HDIM];
__device__ __nv_bfloat16 g_vh[BATCH*NHEAD*SEQ*HDIM];
__device__ __nv_bfloat16 g_vl[BATCH*NHEAD*SEQ*HDIM];
__device__ float g_ao[MROWS*EMBED];           // attention out, [B,T,E] (tf32-rounded)

__device__ __forceinline__ uint32_t f2tf32(float x) {
    uint32_t r;
    asm("cvt.rna.tf32.f32 %0, %1;" : "=r"(r) : "f"(x));
    return r;
}

// ---------------------------------------------------------------------------
// Prepass: round inputs + weights to tf32 into device copies.
// 4,194,304 float4 elements total: [q 1M][k 1M][v 1M][Wq..Wo 256K each].
// ---------------------------------------------------------------------------
__global__ __launch_bounds__(256) void prepass(
    const float* __restrict__ q, const float* __restrict__ k, const float* __restrict__ v,
    const float* __restrict__ Wq, const float* __restrict__ Wk,
    const float* __restrict__ Wv, const float* __restrict__ Wo)
{
    int idx = blockIdx.x * 256 + threadIdx.x;       // float4 index
    const float* src; float* dst; int off;
    if (idx < 3145728) {
        int seg = idx >> 20;            // /1048576
        off = idx & 1048575;
        src = (seg == 0) ? q : (seg == 1) ? k : v;
        dst = (seg == 0) ? g_qc : (seg == 1) ? g_kc : g_vc;
    } else {
        int r = idx - 3145728;
        int seg = r >> 18;              // /262144
        off = r & 262143;
        src = (seg == 0) ? Wq : (seg == 1) ? Wk : (seg == 2) ? Wv : Wo;
        dst = g_w4 + (size_t)seg * EMBED * EMBED;
        dst += 0;
        // off is float4 offset within this weight
    }
    float4 x = reinterpret_cast<const float4*>(src)[off];
    uint4 t = make_uint4(f2tf32(x.x), f2tf32(x.y), f2tf32(x.z), f2tf32(x.w));
    reinterpret_cast<uint4*>(dst)[off] = t;
}

// ---------------------------------------------------------------------------
// TF32 tensor-core GEMM: C = A @ W^T + bias. Inputs pre-rounded to tf32.
// cp.async double-buffered BK=32, pitch 36 (conflict-free frags), 2 CTAs/SM.
// ---------------------------------------------------------------------------
__device__ __forceinline__ void mma_tf32(float* c, const uint32_t* a,
                                         uint32_t b0, uint32_t b1) {
    asm volatile(
        "mma.sync.aligned.m16n8k8.row.col.f32.tf32.tf32.f32 "
        "{%0,%1,%2,%3}, {%4,%5,%6,%7}, {%8,%9}, {%0,%1,%2,%3};"
        : "+f"(c[0]), "+f"(c[1]), "+f"(c[2]), "+f"(c[3])
        : "r"(a[0]), "r"(a[1]), "r"(a[2]), "r"(a[3]), "r"(b0), "r"(b1));
}

__device__ __forceinline__ uint32_t smem_u32(const void* p) {
    uint32_t a;
    asm("{ .reg .u64 t; cvta.to.shared.u64 t, %1; cvt.u32.u64 %0, t; }" : "=r"(a) : "l"(p));
    return a;
}

#define GP 36                    // words per row (32 + 4 pad)
#define GA_WORDS (128*GP)        // 4608 words
#define GSTAGE   (2*GA_WORDS)    // A + W per stage
#define GEMM_SMEM (2*GSTAGE*4)   // 73728 bytes

// BHTD: write bf16 hi/lo to Ch/Cl ([B,H,T,D]); else fp32 to Cf ([M,E]).
template<bool BHTD>
__device__ __forceinline__ void gemm_body(
    const float* __restrict__ A, const float* __restrict__ W,
    const float* __restrict__ bias, float* __restrict__ Cf,
    __nv_bfloat16* __restrict__ Ch, __nv_bfloat16* __restrict__ Cl,
    int m0, int n0)
{
    const int K = EMBED;
    extern __shared__ uint32_t gsm[];
    uint32_t sbase = smem_u32(gsm);

    int tid  = threadIdx.x;
    int lane = tid & 31;
    int warp = tid >> 5;
    int wm = warp >> 1, wn = warp & 1;
    int m0w = wm * 32, n0w = wn * 64;

    float c[2][8][4];
    #pragma unroll
    for (int mi = 0; mi < 2; mi++)
        #pragma unroll
        for (int ni = 0; ni < 8; ni++)
            #pragma unroll
            for (int q = 0; q < 4; q++) c[mi][ni][q] = 0.f;

    auto issue = [&](int k0, int s) {
        #pragma unroll
        for (int i = 0; i < 4; i++) {
            int idx = tid + i*256;
            int r = idx >> 3, c4 = (idx & 7) << 2;
            uint32_t da = sbase + (uint32_t)(s*GSTAGE + r*GP + c4) * 4u;
            const float* ga = A + (size_t)(m0 + r) * K + k0 + c4;
            asm volatile("cp.async.cg.shared.global [%0], [%1], 16;" :: "r"(da), "l"(ga));
            uint32_t dw = da + GA_WORDS * 4u;
            const float* gw = W + (size_t)(n0 + r) * K + k0 + c4;
            asm volatile("cp.async.cg.shared.global [%0], [%1], 16;" :: "r"(dw), "l"(gw));
        }
        asm volatile("cp.async.commit_group;" ::: "memory");
    };

    issue(0, 0);

    const int NCHUNK = K / 32;   // 32
    for (int ch = 0; ch < NCHUNK; ch++) {
        asm volatile("cp.async.wait_group 0;" ::: "memory");
        __syncthreads();
        if (ch + 1 < NCHUNK) issue((ch + 1) * 32, (ch + 1) & 1);

        const uint32_t* As = gsm + (ch & 1) * GSTAGE;
        const uint32_t* Ws = As + GA_WORDS;
        #pragma unroll
        for (int kk = 0; kk < 32; kk += 8) {
            int kb = kk + (lane & 3);
            uint32_t a[2][4];
            #pragma unroll
            for (int mi = 0; mi < 2; mi++) {
                int r = m0w + mi * 16 + (lane >> 2);
                a[mi][0] = As[r*GP + kb];
                a[mi][1] = As[(r + 8)*GP + kb];
                a[mi][2] = As[r*GP + kb + 4];
                a[mi][3] = As[(r + 8)*GP + kb + 4];
            }
            #pragma unroll
            for (int ni = 0; ni < 8; ni++) {
                int rn = n0w + ni * 8 + (lane >> 2);
                uint32_t b0 = Ws[rn*GP + kb];
                uint32_t b1 = Ws[rn*GP + kb + 4];
                mma_tf32(c[0][ni], a[0], b0, b1);
                mma_tf32(c[1][ni], a[1], b0, b1);
            }
        }
        __syncthreads();   // all reads of this stage done before it is refilled
    }

    #pragma unroll
    for (int mi = 0; mi < 2; mi++) {
        int rbase = m0 + m0w + mi * 16 + (lane >> 2);
        #pragma unroll
        for (int ni = 0; ni < 8; ni++) {
            int col = n0 + n0w + ni * 8 + 2 * (lane & 3);    // even
            float bv0 = bias[col], bv1 = bias[col + 1];
            #pragma unroll
            for (int half = 0; half < 2; half++) {
                int m = rbase + half * 8;
                float v0 = c[mi][ni][half * 2 + 0] + bv0;
                float v1 = c[mi][ni][half * 2 + 1] + bv1;
                if (BHTD) {
                    int b = m >> 11, t = m & 2047;
                    int h = col >> 6, d = col & 63;          // d even, d+1 same head
                    size_t base = (((size_t)(b * NHEAD + h)) * SEQ + t) * HDIM + d;
                    __nv_bfloat16 h0 = __float2bfloat16(v0), h1 = __float2bfloat16(v1);
                    __nv_bfloat162 hp; hp.x = h0; hp.y = h1;
                    __nv_bfloat162 lp;
                    lp.x = __float2bfloat16(v0 - __bfloat162float(h0));
                    lp.y = __float2bfloat16(v1 - __bfloat162float(h1));
                    reinterpret_cast<uint32_t*>(Ch)[base >> 1] = *reinterpret_cast<uint32_t*>(&hp);
                    reinterpret_cast<uint32_t*>(Cl)[base >> 1] = *reinterpret_cast<uint32_t*>(&lp);
                } else {
                    Cf[(size_t)m * EMBED + col]     = v0;
                    Cf[(size_t)m * EMBED + col + 1] = v1;
                }
            }
        }
    }
}

__global__ __launch_bounds__(256, 2) void gemm_qkv(
    const float* __restrict__ bq, const float* __restrict__ bk, const float* __restrict__ bv)
{
    int z = blockIdx.z;
    const float* A = (z == 0) ? g_qc : (z == 1) ? g_kc : g_vc;
    const float* W = g_w4 + (size_t)z * EMBED * EMBED;
    const float* B = (z == 0) ? bq : (z == 1) ? bk : bv;
    __nv_bfloat16* Ch = (z == 0) ? g_qh : (z == 1) ? g_kh : g_vh;
    __nv_bfloat16* Cl = (z == 0) ? g_ql : (z == 1) ? g_kl : g_vl;
    gemm_body<true>(A, W, B, nullptr, Ch, Cl, blockIdx.y * 128, blockIdx.x * 128);
}

__global__ __launch_bounds__(256, 2) void gemm_out(
    const float* __restrict__ bias, float* __restrict__ C)
{
    gemm_body<false>(g_ao, g_w4 + (size_t)3 * EMBED * EMBED, bias, C,
                     nullptr, nullptr, blockIdx.y * 128, blockIdx.x * 128);
}

// ---------------------------------------------------------------------------
// Flash attention via bf16 split mma (hi+lo), R7 core; staging from
// pre-split bf16 arrays (pure copy, no conversion), register prefetch.
// ---------------------------------------------------------------------------
__device__ __forceinline__ void mma_bf16(float* c, const uint32_t* a,
                                         uint32_t b0, uint32_t b1) {
    asm volatile(
        "mma.sync.aligned.m16n8k16.row.col.f32.bf16.bf16.f32 "
        "{%0,%1,%2,%3}, {%4,%5,%6,%7}, {%8,%9}, {%0,%1,%2,%3};"
        : "+f"(c[0]), "+f"(c[1]), "+f"(c[2]), "+f"(c[3])
        : "r"(a[0]), "r"(a[1]), "r"(a[2]), "r"(a[3]), "r"(b0), "r"(b1));
}

__device__ __forceinline__ void pack2(float x, float y, uint32_t& hi, uint32_t& lo) {
    __nv_bfloat16 hx = __float2bfloat16(x), hy = __float2bfloat16(y);
    __nv_bfloat162 h2; h2.x = hx; h2.y = hy;
    hi = *reinterpret_cast<uint32_t*>(&h2);
    __nv_bfloat162 l2;
    l2.x = __float2bfloat16(x - __bfloat162float(hx));
    l2.y = __float2bfloat16(y - __bfloat162float(hy));
    lo = *reinterpret_cast<uint32_t*>(&l2);
}

#define FPITCH 72
#define FLASH_SMEM ((128*2 + 64*4) * FPITCH * 2 + 64 * 4)   // 73984

__global__ __launch_bounds__(256, 1) void flash_attn_mma(const unsigned char* __restrict__ mask)
{
    extern __shared__ __align__(16) char smraw[];
    __nv_bfloat16* sQh = (__nv_bfloat16*)smraw;
    __nv_bfloat16* sQl = sQh + 128*FPITCH;
    __nv_bfloat16* sKh = sQl + 128*FPITCH;
    __nv_bfloat16* sKl = sKh + 64*FPITCH;
    __nv_bfloat16* sVh = sKl + 64*FPITCH;     // transposed: [d][s]
    __nv_bfloat16* sVl = sVh + 64*FPITCH;
    float* mfs = (float*)(sVl + 64*FPITCH);   // 64 floats

    int tid  = threadIdx.x;
    int lane = tid & 31, warp = tid >> 5;
    int grp  = lane >> 2, thr4 = lane & 3;
    int qt = (int)gridDim.x - 1 - (int)blockIdx.x;   // heavy tiles first
    int h = blockIdx.y, b = blockIdx.z;
    int qbase = qt * 128;

    size_t headoff = ((size_t)(b*NHEAD + h))*SEQ*HDIM;
    const uint32_t* Qh32 = (const uint32_t*)g_qh + (headoff + (size_t)qbase*HDIM)/2;
    const uint32_t* Ql32 = (const uint32_t*)g_ql + (headoff + (size_t)qbase*HDIM)/2;
    const uint32_t* Kh32 = (const uint32_t*)g_kh + headoff/2;
    const uint32_t* Kl32 = (const uint32_t*)g_kl + headoff/2;
    const uint32_t* Vh32 = (const uint32_t*)g_vh + headoff/2;
    const uint32_t* Vl32 = (const uint32_t*)g_vl + headoff/2;
    const unsigned char* km = mask + (size_t)b*SEQ;

    // ---- stage Q (pure copy) ----
    #pragma unroll
    for (int i = 0; i < 8; i++) {
        int e = tid + i*256;
        int r = e >> 4, c4 = (e & 15) << 2;
        int gi = (r*HDIM + c4) >> 1;
        *reinterpret_cast<uint2*>(sQh + r*FPITCH + c4) = *reinterpret_cast<const uint2*>(Qh32 + gi);
        *reinterpret_cast<uint2*>(sQl + r*FPITCH + c4) = *reinterpret_cast<const uint2*>(Ql32 + gi);
    }

    int lr = tid >> 4;               // 0..15 base row
    int lc4 = (tid & 15) << 2;       // 0..60

    // prefetch tile 0
    uint2 khr[4], klr[4], vhr[4], vlr[4];
    #pragma unroll
    for (int i = 0; i < 4; i++) {
        int gi = ((lr + i*16)*HDIM + lc4) >> 1;
        khr[i] = *reinterpret_cast<const uint2*>(Kh32 + gi);
        klr[i] = *reinterpret_cast<const uint2*>(Kl32 + gi);
        vhr[i] = *reinterpret_cast<const uint2*>(Vh32 + gi);
        vlr[i] = *reinterpret_cast<const uint2*>(Vl32 + gi);
    }
    unsigned char mreg = (tid < 64) ? km[tid] : 0;

    __syncthreads();

    // ---- preload Q fragments ----
    uint32_t qh[4][4], ql[4][4];
    {
        int rl = warp*16 + grp;
        #pragma unroll
        for (int ks = 0; ks < 4; ks++) {
            int cc = thr4*2 + ks*16;
            qh[ks][0] = *(const uint32_t*)(sQh + rl*FPITCH + cc);
            qh[ks][1] = *(const uint32_t*)(sQh + (rl+8)*FPITCH + cc);
            qh[ks][2] = *(const uint32_t*)(sQh + rl*FPITCH + cc + 8);
            qh[ks][3] = *(const uint32_t*)(sQh + (rl+8)*FPITCH + cc + 8);
            ql[ks][0] = *(const uint32_t*)(sQl + rl*FPITCH + cc);
            ql[ks][1] = *(const uint32_t*)(sQl + (rl+8)*FPITCH + cc);
            ql[ks][2] = *(const uint32_t*)(sQl + rl*FPITCH + cc + 8);
            ql[ks][3] = *(const uint32_t*)(sQl + (rl+8)*FPITCH + cc + 8);
        }
    }

    int row0 = qbase + warp*16 + grp;
    int row1 = row0 + 8;

    float m0 = -1e30f, m1 = -1e30f, l0 = 0.f, l1 = 0.f;
    float o[8][4];
    #pragma unroll
    for (int j = 0; j < 8; j++)
        #pragma unroll
        for (int q = 0; q < 4; q++) o[j][q] = 0.f;

    const int ntiles = 2*qt + 2;
    for (int jt = 0; jt < ntiles; jt++) {
        int s0 = jt * 64;
        __syncthreads();
        // store prefetched K/V (copy; V scattered transposed)
        #pragma unroll
        for (int i = 0; i < 4; i++) {
            int r = lr + i*16;
            *reinterpret_cast<uint2*>(sKh + r*FPITCH + lc4) = khr[i];
            *reinterpret_cast<uint2*>(sKl + r*FPITCH + lc4) = klr[i];
            __nv_bfloat162 vh0 = *reinterpret_cast<__nv_bfloat162*>(&vhr[i].x);
            __nv_bfloat162 vh1 = *reinterpret_cast<__nv_bfloat162*>(&vhr[i].y);
            __nv_bfloat162 vl0 = *reinterpret_cast<__nv_bfloat162*>(&vlr[i].x);
            __nv_bfloat162 vl1 = *reinterpret_cast<__nv_bfloat162*>(&vlr[i].y);
            sVh[(lc4+0)*FPITCH + r] = vh0.x;
            sVh[(lc4+1)*FPITCH + r] = vh0.y;
            sVh[(lc4+2)*FPITCH + r] = vh1.x;
            sVh[(lc4+3)*FPITCH + r] = vh1.y;
            sVl[(lc4+0)*FPITCH + r] = vl0.x;
            sVl[(lc4+1)*FPITCH + r] = vl0.y;
            sVl[(lc4+2)*FPITCH + r] = vl1.x;
            sVl[(lc4+3)*FPITCH + r] = vl1.y;
        }
        if (tid < 64) mfs[tid] = mreg ? -1e30f : 0.0f;
        __syncthreads();

        // prefetch next tile while mmas run
        if (jt + 1 < ntiles) {
            #pragma unroll
            for (int i = 0; i < 4; i++) {
                int gi = ((s0 + 64 + lr + i*16)*HDIM + lc4) >> 1;
                khr[i] = *reinterpret_cast<const uint2*>(Kh32 + gi);
                klr[i] = *reinterpret_cast<const uint2*>(Kl32 + gi);
                vhr[i] = *reinterpret_cast<const uint2*>(Vh32 + gi);
                vlr[i] = *reinterpret_cast<const uint2*>(Vl32 + gi);
            }
            if (tid < 64) mreg = km[s0 + 64 + tid];
        }

        // ---- S = Q K^T ----
        float s[8][4];
        #pragma unroll
        for (int j = 0; j < 8; j++)
            #pragma unroll
            for (int q = 0; q < 4; q++) s[j][q] = 0.f;

        #pragma unroll
        for (int ks = 0; ks < 4; ks++) {
            int cc = thr4*2 + ks*16;
            #pragma unroll
            for (int j = 0; j < 8; j++) {
                int n = j*8 + grp;
                uint32_t bh0 = *(const uint32_t*)(sKh + n*FPITCH + cc);
                uint32_t bh1 = *(const uint32_t*)(sKh + n*FPITCH + cc + 8);
                uint32_t bl0 = *(const uint32_t*)(sKl + n*FPITCH + cc);
                uint32_t bl1 = *(const uint32_t*)(sKl + n*FPITCH + cc + 8);
                mma_bf16(s[j], qh[ks], bh0, bh1);
                mma_bf16(s[j], qh[ks], bl0, bl1);
                mma_bf16(s[j], ql[ks], bh0, bh1);
            }
        }

        // ---- scale + masks + online softmax ----
        bool diag = (jt >= 2*qt);
        float nm0 = m0, nm1 = m1;
        #pragma unroll
        for (int j = 0; j < 8; j++) {
            int cb = 8*j + 2*thr4;
            float f0 = mfs[cb], f1 = mfs[cb+1];
            float v00 = fmaf(s[j][0], 0.125f, f0);
            float v01 = fmaf(s[j][1], 0.125f, f1);
            float v10 = fmaf(s[j][2], 0.125f, f0);
            float v11 = fmaf(s[j][3], 0.125f, f1);
            if (diag) {
                int ca = s0 + cb;
                if (ca     > row0) v00 = -1e30f;
                if (ca + 1 > row0) v01 = -1e30f;
                if (ca     > row1) v10 = -1e30f;
                if (ca + 1 > row1) v11 = -1e30f;
            }
            s[j][0] = v00; s[j][1] = v01; s[j][2] = v10; s[j][3] = v11;
            nm0 = fmaxf(nm0, fmaxf(v00, v01));
            nm1 = fmaxf(nm1, fmaxf(v10, v11));
        }
        nm0 = fmaxf(nm0, __shfl_xor_sync(0xffffffffu, nm0, 1));
        nm0 = fmaxf(nm0, __shfl_xor_sync(0xffffffffu, nm0, 2));
        nm1 = fmaxf(nm1, __shfl_xor_sync(0xffffffffu, nm1, 1));
        nm1 = fmaxf(nm1, __shfl_xor_sync(0xffffffffu, nm1, 2));

        float c0 = __expf(m0 - nm0), c1 = __expf(m1 - nm1);
        m0 = nm0; m1 = nm1;

        float ls0 = 0.f, ls1 = 0.f;
        #pragma unroll
        for (int j = 0; j < 8; j++) {
            s[j][0] = __expf(s[j][0] - m0);
            s[j][1] = __expf(s[j][1] - m0);
            s[j][2] = __expf(s[j][2] - m1);
            s[j][3] = __expf(s[j][3] - m1);
            ls0 += s[j][0] + s[j][1];
            ls1 += s[j][2] + s[j][3];
        }
        ls0 += __shfl_xor_sync(0xffffffffu, ls0, 1);
        ls0 += __shfl_xor_sync(0xffffffffu, ls0, 2);
        ls1 += __shfl_xor_sync(0xffffffffu, ls1, 1);
        ls1 += __shfl_xor_sync(0xffffffffu, ls1, 2);
        l0 = l0*c0 + ls0;
        l1 = l1*c1 + ls1;

        #pragma unroll
        for (int j = 0; j < 8; j++) {
            o[j][0] *= c0; o[j][1] *= c0;
            o[j][2] *= c1; o[j][3] *= c1;
        }

        // ---- O += P V ----
        #pragma unroll
        for (int ks = 0; ks < 4; ks++) {
            uint32_t ph[4], pl[4];
            float* sa = s[2*ks];
            float* sb = s[2*ks + 1];
            pack2(sa[0], sa[1], ph[0], pl[0]);
            pack2(sa[2], sa[3], ph[1], pl[1]);
            pack2(sb[0], sb[1], ph[2], pl[2]);
            pack2(sb[2], sb[3], ph[3], pl[3]);
            int cc = thr4*2 + ks*16;
            #pragma unroll
            for (int j = 0; j < 8; j++) {
                int n = j*8 + grp;
                uint32_t vh0 = *(const uint32_t*)(sVh + n*FPITCH + cc);
                uint32_t vh1 = *(const uint32_t*)(sVh + n*FPITCH + cc + 8);
                uint32_t vl0 = *(const uint32_t*)(sVl + n*FPITCH + cc);
                uint32_t vl1 = *(const uint32_t*)(sVl + n*FPITCH + cc + 8);
                mma_bf16(o[j], ph, vh0, vh1);
                mma_bf16(o[j], ph, vl0, vl1);
                mma_bf16(o[j], pl, vh0, vh1);
            }
        }
    }

    // ---- epilogue: [B,T,E], pre-rounded to tf32 for gemm_out ----
    float inv0 = 1.f / l0, inv1 = 1.f / l1;
    float* O0 = g_ao + ((size_t)(b*SEQ) + row0)*EMBED + h*HDIM;
    float* O1 = g_ao + ((size_t)(b*SEQ) + row1)*EMBED + h*HDIM;
    #pragma unroll
    for (int j = 0; j < 8; j++) {
        int col = 8*j + 2*thr4;
        uint2 r0 = make_uint2(f2tf32(o[j][0]*inv0), f2tf32(o[j][1]*inv0));
        uint2 r1 = make_uint2(f2tf32(o[j][2]*inv1), f2tf32(o[j][3]*inv1));
        *reinterpret_cast<uint2*>(O0 + col) = r0;
        *reinterpret_cast<uint2*>(O1 + col) = r1;
    }
}

// ---------------------------------------------------------------------------
extern "C" void kernel_launch(void* const* d_in, const int* in_sizes, int n_in,
                              void* d_out, int out_size)
{
    const float* query = (const float*)d_in[0];
    const float* key   = (const float*)d_in[1];
    const float* value = (const float*)d_in[2];
    const unsigned char* kpm = (const unsigned char*)d_in[3];
    const float* Wq = (const float*)d_in[4];
    const float* bq = (const float*)d_in[5];
    const float* Wk = (const float*)d_in[6];
    const float* bk = (const float*)d_in[7];
    const float* Wv = (const float*)d_in[8];
    const float* bv = (const float*)d_in[9];
    const float* Wo = (const float*)d_in[10];
    const float* bo = (const float*)d_in[11];
    float* out = (float*)d_out;

    prepass<<<16384, 256>>>(query, key, value, Wq, Wk, Wv, Wo);

    cudaFuncSetAttribute(gemm_qkv, cudaFuncAttributeMaxDynamicSharedMemorySize, GEMM_SMEM);
    cudaFuncSetAttribute(gemm_out, cudaFuncAttributeMaxDynamicSharedMemorySize, GEMM_SMEM);

    dim3 gqkv(EMBED/128, MROWS/128, 3);   // (8, 32, 3)
    gemm_qkv<<<gqkv, 256, GEMM_SMEM>>>(bq, bk, bv);

    cudaFuncSetAttribute(flash_attn_mma, cudaFuncAttributeMaxDynamicSharedMemorySize, FLASH_SMEM);
    flash_attn_mma<<<dim3(SEQ/128, NHEAD, BATCH), 256, FLASH_SMEM>>>(kpm);

    dim3 gout(EMBED/128, MROWS/128);
    gemm_out<<<gout, 256, GEMM_SMEM>>>(bo, out);
}